// round 11
// baseline (speedup 1.0000x reference)
#include <cuda_runtime.h>
#include <cuda_bf16.h>
#include <cuda_fp16.h>
#include <math.h>
#include <stdint.h>

// Problem constants
#define Bb 2
#define Tt 2048
#define Cc 1024
#define Hh 16
#define Dd 64
#define Mm (Bb*Tt)           // 4096 tokens
#define ATT_SCALE 0.125f     // D^-0.5

// ---------------- scratch (device globals; no allocations allowed) ----------
__device__ float g_r1[Mm*Cc];
__device__ float g_part[64*Bb*Cc];
__device__ float g_mean[Bb*Cc];

// fp16 buffers (activations hi/lo, weights single)
__device__ __half g_xh[Mm*Cc],  g_xl[Mm*Cc];
__device__ __half g_rth[Mm*Cc], g_rtl[Mm*Cc];
__device__ __half g_ath[Mm*Cc], g_atl[Mm*Cc];
__device__ __half g_qh[Mm*Cc],  g_ql[Mm*Cc];
__device__ __half g_kf[Mm*Cc],  g_vf[Mm*Cc];
__device__ __half g_wq[Cc*Cc], g_wk[Cc*Cc], g_wv[Cc*Cc];
__device__ __half g_wo[Cc*Cc], g_wr1[Cc*Cc];

// ================= PTX helpers (sm_100 baseline ISA only) ====================
__device__ __forceinline__ uint32_t smem_u32(const void* p) {
    uint32_t a;
    asm("{ .reg .u64 t; cvta.to.shared.u64 t, %1; cvt.u32.u64 %0, t; }"
        : "=r"(a) : "l"(p));
    return a;
}
__device__ __forceinline__ void cpasync16(uint32_t dst, const void* src) {
    asm volatile("cp.async.cg.shared.global [%0], [%1], 16;" :: "r"(dst), "l"(src));
}
__device__ __forceinline__ void ldsm4(uint32_t& r0, uint32_t& r1, uint32_t& r2,
                                      uint32_t& r3, uint32_t addr) {
    asm volatile("ldmatrix.sync.aligned.m8n8.x4.shared.b16 {%0,%1,%2,%3}, [%4];"
        : "=r"(r0), "=r"(r1), "=r"(r2), "=r"(r3) : "r"(addr));
}
__device__ __forceinline__ void ldsm4t(uint32_t& r0, uint32_t& r1, uint32_t& r2,
                                       uint32_t& r3, uint32_t addr) {
    asm volatile("ldmatrix.sync.aligned.m8n8.x4.trans.shared.b16 {%0,%1,%2,%3}, [%4];"
        : "=r"(r0), "=r"(r1), "=r"(r2), "=r"(r3) : "r"(addr));
}
__device__ __forceinline__ void mma16816h(float* d, const uint32_t* a, const uint32_t* b) {
    asm volatile(
        "mma.sync.aligned.m16n8k16.row.col.f32.f16.f16.f32 "
        "{%0,%1,%2,%3}, {%4,%5,%6,%7}, {%8,%9}, {%0,%1,%2,%3};"
        : "+f"(d[0]), "+f"(d[1]), "+f"(d[2]), "+f"(d[3])
        : "r"(a[0]), "r"(a[1]), "r"(a[2]), "r"(a[3]), "r"(b[0]), "r"(b[1]));
}
__device__ __forceinline__ uint32_t pack_h2(float a, float b) {
    __half2 h = __floats2half2_rn(a, b);
    return *(uint32_t*)&h;
}
__device__ __forceinline__ float h_lo_res(float v, uint32_t pk) {
    __half2 h2 = *(__half2*)&pk;
    return v - __low2float(h2);
}
__device__ __forceinline__ float h_hi_res(float v, uint32_t pk) {
    __half2 h2 = *(__half2*)&pk;
    return v - __high2float(h2);
}

// ---------------- mean pool (deterministic two-stage) -----------------------
__global__ __launch_bounds__(256) void mean_part_kernel(const float* __restrict__ x) {
    int c  = blockIdx.x * 256 + threadIdx.x;
    int b  = blockIdx.z;
    int t0 = blockIdx.y * (Tt / 64);
    float s = 0.f;
    #pragma unroll 8
    for (int tt = 0; tt < Tt / 64; tt++)
        s += x[((size_t)b * Tt + t0 + tt) * Cc + c];
    g_part[((size_t)blockIdx.y * Bb + b) * Cc + c] = s;
}

__global__ __launch_bounds__(256) void mean_reduce_kernel() {
    int idx = blockIdx.x * 256 + threadIdx.x;
    if (idx < Bb * Cc) {
        float s = 0.f;
        #pragma unroll
        for (int u = 0; u < 64; u++) s += g_part[(size_t)u * Bb * Cc + idx];
        g_mean[idx] = s * (1.0f / (float)Tt);
    }
}

// ---------------- conversions ------------------------------------------------
__global__ __launch_bounds__(256) void cvt_hilo16_kernel(
    const float* __restrict__ x, __half* __restrict__ hi,
    __half* __restrict__ lo, int n4)
{
    int i = blockIdx.x * 256 + threadIdx.x;
    if (i >= n4) return;
    float4 v = ((const float4*)x)[i];
    uint32_t h0 = pack_h2(v.x, v.y);
    uint32_t h1 = pack_h2(v.z, v.w);
    uint2 hh; hh.x = h0; hh.y = h1;
    uint2 ll;
    ll.x = pack_h2(h_lo_res(v.x, h0), h_hi_res(v.y, h0));
    ll.y = pack_h2(h_lo_res(v.z, h1), h_hi_res(v.w, h1));
    ((uint2*)hi)[i] = hh;
    ((uint2*)lo)[i] = ll;
}

struct CvtW5 {
    const float* src[5];
    __half* dst[5];
};
__global__ __launch_bounds__(256) void cvt_w_kernel(CvtW5 b, int n4) {
    int t = blockIdx.y;
    int i = blockIdx.x * 256 + threadIdx.x;
    if (i >= n4) return;
    float4 v = ((const float4*)b.src[t])[i];
    uint2 o;
    o.x = pack_h2(v.x, v.y);
    o.y = pack_h2(v.z, v.w);
    ((uint2*)b.dst[t])[i] = o;
}

// ================= HMMA GEMM (fp16 2-term, multi-job) ========================
// Y[M,N] = A[M,K] @ W[N,K]^T + bias,  A = Ah + Al (fp16 split), W fp16 single.
// CTA 128x128, BK=64, stage {Ah,Al,W}, 2-stage cp.async, 2 CTAs/SM.
// blockIdx.z selects job. Mode: 0 fp32; 1 tanh fp32; 2 fp16 hi/lo; 3 fp16.
#define G_NCH 16
#define G_LD 72
#define G_TILE (128 * G_LD * 2)             // 18432 bytes per tensor tile
#define G_STAGE_BYTES (3 * G_TILE)          // 55296
#define G_SMEM_BYTES (2 * G_STAGE_BYTES)    // 110592

struct GJob {
    const __half *Ah, *Al, *W;
    const float* bias;
    float* out;
    __half *oh, *ol;
    float scale;
    int mode;
};
struct GJobs { GJob j[2]; };

__global__ __launch_bounds__(256, 2) void gemm_multi(GJobs jobs)
{
    extern __shared__ __align__(16) uint8_t gsm[];
    uint32_t base = smem_u32(gsm);

    const GJob jb = jobs.j[blockIdx.z];
    const __half* __restrict__ Ah = jb.Ah;
    const __half* __restrict__ Al = jb.Al;
    const __half* __restrict__ W  = jb.W;

    int tid = threadIdx.x;
    int wid = tid >> 5;
    int l   = tid & 31;
    int wm  = wid >> 1;
    int wn  = wid & 1;
    int m0  = blockIdx.y * 128;
    int n0  = blockIdx.x * 128;

    int lrow = tid >> 3;
    int lc16 = tid & 7;

    int arow = wm * 32 + (l & 15);
    int akc  = (l >> 4) * 8;
    int brow_in = (l & 7) + ((l >> 4) & 1) * 8;
    int bkc  = ((l >> 3) & 1) * 8;

    float acc[2][8][4];
    #pragma unroll
    for (int i = 0; i < 2; i++)
        #pragma unroll
        for (int j = 0; j < 8; j++)
            #pragma unroll
            for (int u = 0; u < 4; u++) acc[i][j][u] = 0.f;

    auto load_tile = [&](int c, int s) {
        int k0 = c * 64;
        uint32_t sb = base + s * G_STAGE_BYTES;
        #pragma unroll
        for (int it = 0; it < 4; it++) {
            int row = lrow + it * 32;
            uint32_t off = (row * G_LD + lc16 * 8) * 2;
            cpasync16(sb + off, Ah + (size_t)(m0 + row) * Cc + k0 + lc16 * 8);
            cpasync16(sb + G_TILE + off, Al + (size_t)(m0 + row) * Cc + k0 + lc16 * 8);
            cpasync16(sb + 2 * G_TILE + off, W + (size_t)(n0 + row) * Cc + k0 + lc16 * 8);
        }
    };

    load_tile(0, 0);
    asm volatile("cp.async.commit_group;");

    for (int c = 0; c < G_NCH; c++) {
        asm volatile("cp.async.wait_group 0;");
        __syncthreads();
        if (c + 1 < G_NCH) {
            load_tile(c + 1, (c + 1) & 1);
            asm volatile("cp.async.commit_group;");
        }

        uint32_t ab = base + (c & 1) * G_STAGE_BYTES;
        uint32_t lb = ab + G_TILE;
        uint32_t wb = ab + 2 * G_TILE;
        #pragma unroll
        for (int ks = 0; ks < 4; ks++) {
            uint32_t ah[2][4], al[2][4];
            #pragma unroll
            for (int i = 0; i < 2; i++) {
                uint32_t ro = ((arow + i * 16) * G_LD + akc + ks * 16) * 2;
                ldsm4(ah[i][0], ah[i][1], ah[i][2], ah[i][3], ab + ro);
                ldsm4(al[i][0], al[i][1], al[i][2], al[i][3], lb + ro);
            }
            uint32_t wf[4][4];
            #pragma unroll
            for (int nn = 0; nn < 4; nn++)
                ldsm4(wf[nn][0], wf[nn][1], wf[nn][2], wf[nn][3],
                      wb + ((wn * 64 + nn * 16 + brow_in) * G_LD + bkc + ks * 16) * 2);
            #pragma unroll
            for (int i = 0; i < 2; i++)
                #pragma unroll
                for (int j = 0; j < 8; j++) {
                    mma16816h(acc[i][j], ah[i], &wf[j >> 1][(j & 1) * 2]);
                    mma16816h(acc[i][j], al[i], &wf[j >> 1][(j & 1) * 2]);
                }
        }
    }

    // epilogue (mode uniform per CTA)
    int mode = jb.mode;
    float scale = jb.scale;
    #pragma unroll
    for (int i = 0; i < 2; i++) {
        int row = m0 + wm * 32 + i * 16 + (l >> 2);
        #pragma unroll
        for (int j = 0; j < 8; j++) {
            int col = n0 + wn * 64 + j * 8 + (l & 3) * 2;
            float b0v = __ldg(&jb.bias[col]);
            float b1v = __ldg(&jb.bias[col + 1]);
            float v0 = acc[i][j][0] + b0v;
            float v1 = acc[i][j][1] + b1v;
            float v2 = acc[i][j][2] + b0v;
            float v3 = acc[i][j][3] + b1v;
            if (mode == 1) {
                v0 = tanhf(v0); v1 = tanhf(v1);
                v2 = tanhf(v2); v3 = tanhf(v3);
            }
            if (mode == 2) {
                v0 *= scale; v1 *= scale; v2 *= scale; v3 *= scale;
                uint32_t h0 = pack_h2(v0, v1);
                uint32_t h1 = pack_h2(v2, v3);
                *(uint32_t*)(jb.oh + (size_t)row * Cc + col) = h0;
                *(uint32_t*)(jb.oh + (size_t)(row + 8) * Cc + col) = h1;
                *(uint32_t*)(jb.ol + (size_t)row * Cc + col) =
                    pack_h2(h_lo_res(v0, h0), h_hi_res(v1, h0));
                *(uint32_t*)(jb.ol + (size_t)(row + 8) * Cc + col) =
                    pack_h2(h_lo_res(v2, h1), h_hi_res(v3, h1));
            } else if (mode == 3) {
                *(uint32_t*)(jb.oh + (size_t)row * Cc + col) = pack_h2(v0, v1);
                *(uint32_t*)(jb.oh + (size_t)(row + 8) * Cc + col) = pack_h2(v2, v3);
            } else {
                float2 p0; p0.x = v0; p0.y = v1;
                float2 p1; p1.x = v2; p1.y = v3;
                *(float2*)(jb.out + (size_t)row * Cc + col) = p0;
                *(float2*)(jb.out + (size_t)(row + 8) * Cc + col) = p1;
            }
        }
    }
}

// ---------------- routing: logits -> softmax -> routed (fp16 hi/lo) ---------
__global__ __launch_bounds__(128) void routing_kernel(
    const float* __restrict__ r1, const float* __restrict__ Wr2,
    const float* __restrict__ br2, const float* __restrict__ x,
    __half* __restrict__ rth, __half* __restrict__ rtl)
{
    int t = blockIdx.x;
    int b = t >> 11;
    int tid = threadIdx.x;

    const float* rrow = r1 + (size_t)t * Cc;
    float s0 = 0.f, s1 = 0.f, s2 = 0.f;
    for (int c = tid; c < Cc; c += 128) {
        float vv = rrow[c];
        s0 = fmaf(vv, Wr2[c],          s0);
        s1 = fmaf(vv, Wr2[Cc + c],     s1);
        s2 = fmaf(vv, Wr2[2 * Cc + c], s2);
    }
    #pragma unroll
    for (int o = 16; o; o >>= 1) {
        s0 += __shfl_xor_sync(0xffffffffu, s0, o);
        s1 += __shfl_xor_sync(0xffffffffu, s1, o);
        s2 += __shfl_xor_sync(0xffffffffu, s2, o);
    }
    __shared__ float red[3][4];
    __shared__ float wsh[2];
    if ((tid & 31) == 0) {
        red[0][tid >> 5] = s0; red[1][tid >> 5] = s1; red[2][tid >> 5] = s2;
    }
    __syncthreads();
    if (tid == 0) {
        float l0 = red[0][0] + red[0][1] + red[0][2] + red[0][3] + br2[0];
        float l1 = red[1][0] + red[1][1] + red[1][2] + red[1][3] + br2[1];
        float l2 = red[2][0] + red[2][1] + red[2][2] + red[2][3] + br2[2];
        float mx = fmaxf(l0, fmaxf(l1, l2));
        float e0 = expf(l0 - mx), e1 = expf(l1 - mx), e2 = expf(l2 - mx);
        float inv = 1.0f / (e0 + e1 + e2);
        wsh[0] = e0 * inv; wsh[1] = e1 * inv;
    }
    __syncthreads();
    float w0 = wsh[0], w1 = wsh[1];

    const float4* x4 = (const float4*)(x + (size_t)t * Cc);
    const float4* m4 = (const float4*)(g_mean + (size_t)b * Cc);
    uint2* ho = (uint2*)(rth + (size_t)t * Cc);
    uint2* lo = (uint2*)(rtl + (size_t)t * Cc);
    for (int c4 = tid; c4 < Cc / 4; c4 += 128) {
        float4 xv = x4[c4], mv = m4[c4];
        float r0 = xv.x * w0 + mv.x * w1;
        float r1v = xv.y * w0 + mv.y * w1;
        float r2 = xv.z * w0 + mv.z * w1;
        float r3 = xv.w * w0 + mv.w * w1;
        uint32_t h0 = pack_h2(r0, r1v);
        uint32_t h1 = pack_h2(r2, r3);
        uint2 hh; hh.x = h0; hh.y = h1;
        uint2 ll;
        ll.x = pack_h2(h_lo_res(r0, h0), h_hi_res(r1v, h0));
        ll.y = pack_h2(h_lo_res(r2, h1), h_hi_res(r3, h1));
        ho[c4] = hh;
        lo[c4] = ll;
    }
}

// ================= tensor-core flash attention (all fp16) ====================
// CTA: 64 Q rows (4 warps x 16), 128 threads, KV chunks of 64, 3-stage pipe.
// 2 CTAs/SM. S = Qh*K + Ql*K (fp16 2-term); PV = P x V single term.
// (exact R8 configuration — best measured)
#define F_LD 72
#define FQ_HALVES (64 * F_LD)
#define FS_HALVES (64 * F_LD)
#define F_TSTAGE (2 * FS_HALVES)            // K, V
#define F_STAGE0 (2 * FQ_HALVES)
#define F_SMEM_BYTES ((2 * FQ_HALVES + 3 * F_TSTAGE) * 2)   // 73728

__global__ __launch_bounds__(128, 2) void flash_mma(
    const __half* __restrict__ qhp, const __half* __restrict__ qlp,
    const __half* __restrict__ kf, const __half* __restrict__ vf,
    __half* __restrict__ oh, __half* __restrict__ ol)
{
    extern __shared__ __half fsh[];
    uint32_t fsb = smem_u32(fsh);

    int tid = threadIdx.x;
    int w   = tid >> 5;            // 0..3
    int l   = tid & 31;
    int q0  = blockIdx.x * 64;
    int h   = blockIdx.y;
    int b   = blockIdx.z;
    int tokb = b * Tt;
    int hoff = h * Dd;

    // ---- load Q (hi+lo), rides with chunk-0's commit group ----
    {
        const __half* srcs[2] = {qhp, qlp};
        #pragma unroll
        for (int ten = 0; ten < 2; ten++) {
            #pragma unroll
            for (int it = 0; it < 4; it++) {
                int idx = tid + it * 128;          // [0,512)
                int row = idx >> 3, c16 = idx & 7;
                uint32_t dst = fsb + ((ten * FQ_HALVES) + row * F_LD + c16 * 8) * 2;
                cpasync16(dst, srcs[ten] + (size_t)(tokb + q0 + row) * Cc + hoff + c16 * 8);
            }
        }
    }
    auto load_kv = [&](int c, int s) {
        int kt0 = c * 64;
        uint32_t sb = fsb + (F_STAGE0 + s * F_TSTAGE) * 2;
        #pragma unroll
        for (int it = 0; it < 4; it++) {
            int idx = tid + it * 128;              // [0,512)
            int row = idx >> 3, c16 = idx & 7;
            uint32_t off = (row * F_LD + c16 * 8) * 2;
            cpasync16(sb + off, kf + (size_t)(tokb + kt0 + row) * Cc + hoff + c16 * 8);
            cpasync16(sb + FS_HALVES * 2 + off,
                      vf + (size_t)(tokb + kt0 + row) * Cc + hoff + c16 * 8);
        }
    };

    load_kv(0, 0);
    asm volatile("cp.async.commit_group;");
    load_kv(1, 1);
    asm volatile("cp.async.commit_group;");

    int arow = (l & 15);
    int akc  = (l >> 4) * 8;
    int brow_in = (l & 7) + ((l >> 4) & 1) * 8;
    int bkc  = ((l >> 3) & 1) * 8;
    int vrow = (l & 7) + ((l >> 3) & 1) * 8;
    int vcol = ((l >> 4) & 1) * 8;

    uint32_t qh[4][4], ql[4][4];
    float oacc[8][4];
    #pragma unroll
    for (int j = 0; j < 8; j++)
        #pragma unroll
        for (int u = 0; u < 4; u++) oacc[j][u] = 0.f;
    float m0r = -1e30f, m1r = -1e30f, l0r = 0.f, l1r = 0.f;

    const int NCH = Tt / 64;
    for (int c = 0; c < NCH; c++) {
        if (c < NCH - 1) asm volatile("cp.async.wait_group 1;");
        else             asm volatile("cp.async.wait_group 0;");
        __syncthreads();

        if (c == 0) {
            #pragma unroll
            for (int kt = 0; kt < 4; kt++) {
                ldsm4(qh[kt][0], qh[kt][1], qh[kt][2], qh[kt][3],
                      fsb + ((w * 16 + arow) * F_LD + kt * 16 + akc) * 2);
                ldsm4(ql[kt][0], ql[kt][1], ql[kt][2], ql[kt][3],
                      fsb + (FQ_HALVES + (w * 16 + arow) * F_LD + kt * 16 + akc) * 2);
            }
        }

        if (c + 2 < NCH) {
            load_kv(c + 2, (c + 2) % 3);
            asm volatile("cp.async.commit_group;");
        }

        uint32_t SB = F_STAGE0 + (c % 3) * F_TSTAGE;
        uint32_t KF = SB, VF = SB + FS_HALVES;

        // ---- S = Q K^T (fp16 2-term) ----
        float sacc[8][4];
        #pragma unroll
        for (int j = 0; j < 8; j++)
            #pragma unroll
            for (int u = 0; u < 4; u++) sacc[j][u] = 0.f;

        #pragma unroll
        for (int ks = 0; ks < 4; ks++) {
            uint32_t kh[4][4];
            #pragma unroll
            for (int g = 0; g < 4; g++) {
                uint32_t ro = ((g * 16 + brow_in) * F_LD + bkc + ks * 16) * 2;
                ldsm4(kh[g][0], kh[g][1], kh[g][2], kh[g][3], fsb + KF * 2 + ro);
            }
            #pragma unroll
            for (int g = 0; g < 4; g++)
                #pragma unroll
                for (int sub = 0; sub < 2; sub++) {
                    int j = g * 2 + sub;
                    mma16816h(sacc[j], qh[ks], &kh[g][sub * 2]);
                    mma16816h(sacc[j], ql[ks], &kh[g][sub * 2]);
                }
        }

        // ---- online softmax, P packed fp16 ----
        float mx0 = -1e30f, mx1 = -1e30f;
        #pragma unroll
        for (int j = 0; j < 8; j++) {
            mx0 = fmaxf(mx0, fmaxf(sacc[j][0], sacc[j][1]));
            mx1 = fmaxf(mx1, fmaxf(sacc[j][2], sacc[j][3]));
        }
        mx0 = fmaxf(mx0, __shfl_xor_sync(0xffffffffu, mx0, 1));
        mx0 = fmaxf(mx0, __shfl_xor_sync(0xffffffffu, mx0, 2));
        mx1 = fmaxf(mx1, __shfl_xor_sync(0xffffffffu, mx1, 1));
        mx1 = fmaxf(mx1, __shfl_xor_sync(0xffffffffu, mx1, 2));
        float mn0 = fmaxf(m0r, mx0), mn1 = fmaxf(m1r, mx1);
        float cor0 = __expf(m0r - mn0), cor1 = __expf(m1r - mn1);
        m0r = mn0; m1r = mn1;

        uint32_t phf[4][4];
        float rs0 = 0.f, rs1 = 0.f;
        #pragma unroll
        for (int j = 0; j < 8; j++) {
            float e0 = __expf(sacc[j][0] - mn0);
            float e1 = __expf(sacc[j][1] - mn0);
            float e2 = __expf(sacc[j][2] - mn1);
            float e3 = __expf(sacc[j][3] - mn1);
            rs0 += e0 + e1; rs1 += e2 + e3;
            int kt = j >> 1, sl = (j & 1) * 2;
            phf[kt][sl]     = pack_h2(e0, e1);
            phf[kt][sl + 1] = pack_h2(e2, e3);
        }
        rs0 += __shfl_xor_sync(0xffffffffu, rs0, 1);
        rs0 += __shfl_xor_sync(0xffffffffu, rs0, 2);
        rs1 += __shfl_xor_sync(0xffffffffu, rs1, 1);
        rs1 += __shfl_xor_sync(0xffffffffu, rs1, 2);
        l0r = l0r * cor0 + rs0;
        l1r = l1r * cor1 + rs1;
        #pragma unroll
        for (int j = 0; j < 8; j++) {
            oacc[j][0] *= cor0; oacc[j][1] *= cor0;
            oacc[j][2] *= cor1; oacc[j][3] *= cor1;
        }

        // ---- O += P V (fp16, single term) ----
        #pragma unroll
        for (int kt = 0; kt < 4; kt++) {
            #pragma unroll
            for (int dg = 0; dg < 4; dg++) {
                uint32_t vh[4];
                uint32_t ro = ((kt * 16 + vrow) * F_LD + dg * 16 + vcol) * 2;
                ldsm4t(vh[0], vh[1], vh[2], vh[3], fsb + VF * 2 + ro);
                #pragma unroll
                for (int sub = 0; sub < 2; sub++)
                    mma16816h(oacc[dg * 2 + sub], phf[kt], &vh[sub * 2]);
            }
        }
    }

    // ---- epilogue: normalize, fp16 hi/lo split, write ----
    float inv0 = 1.0f / l0r, inv1 = 1.0f / l1r;
    int row0 = tokb + q0 + w * 16 + (l >> 2);
    int row1 = row0 + 8;
    #pragma unroll
    for (int dt = 0; dt < 8; dt++) {
        int col = hoff + dt * 8 + (l & 3) * 2;
        float v0 = oacc[dt][0] * inv0, v1 = oacc[dt][1] * inv0;
        float v2 = oacc[dt][2] * inv1, v3 = oacc[dt][3] * inv1;
        uint32_t h0 = pack_h2(v0, v1);
        uint32_t h1 = pack_h2(v2, v3);
        *(uint32_t*)(oh + (size_t)row0 * Cc + col) = h0;
        *(uint32_t*)(oh + (size_t)row1 * Cc + col) = h1;
        *(uint32_t*)(ol + (size_t)row0 * Cc + col) =
            pack_h2(h_lo_res(v0, h0), h_hi_res(v1, h0));
        *(uint32_t*)(ol + (size_t)row1 * Cc + col) =
            pack_h2(h_lo_res(v2, h1), h_hi_res(v3, h1));
    }
}

// ---------------- host driver -----------------------------------------------
extern "C" void kernel_launch(void* const* d_in, const int* in_sizes, int n_in,
                              void* d_out, int out_size)
{
    const float* x   = (const float*)d_in[0];
    const float* Wq  = (const float*)d_in[1];
    const float* bq  = (const float*)d_in[2];
    const float* Wk  = (const float*)d_in[3];
    const float* bk  = (const float*)d_in[4];
    const float* Wv  = (const float*)d_in[5];
    const float* bv  = (const float*)d_in[6];
    const float* Wo  = (const float*)d_in[7];
    const float* bo  = (const float*)d_in[8];
    const float* Wr1 = (const float*)d_in[9];
    const float* br1 = (const float*)d_in[10];
    const float* Wr2 = (const float*)d_in[11];
    const float* br2 = (const float*)d_in[12];
    float* out = (float*)d_out;

    float* r1;
    cudaGetSymbolAddress((void**)&r1, g_r1);

    __half *xh, *xl, *rth, *rtl, *ath, *atl, *qh, *ql, *kf, *vf;
    __half *wq, *wk, *wv, *wo, *wr1;
    cudaGetSymbolAddress((void**)&xh,  g_xh);  cudaGetSymbolAddress((void**)&xl,  g_xl);
    cudaGetSymbolAddress((void**)&rth, g_rth); cudaGetSymbolAddress((void**)&rtl, g_rtl);
    cudaGetSymbolAddress((void**)&ath, g_ath); cudaGetSymbolAddress((void**)&atl, g_atl);
    cudaGetSymbolAddress((void**)&qh,  g_qh);  cudaGetSymbolAddress((void**)&ql,  g_ql);
    cudaGetSymbolAddress((void**)&kf,  g_kf);  cudaGetSymbolAddress((void**)&vf,  g_vf);
    cudaGetSymbolAddress((void**)&wq,  g_wq);  cudaGetSymbolAddress((void**)&wk,  g_wk);
    cudaGetSymbolAddress((void**)&wv,  g_wv);  cudaGetSymbolAddress((void**)&wo,  g_wo);
    cudaGetSymbolAddress((void**)&wr1, g_wr1);

    cudaFuncSetAttribute(gemm_multi, cudaFuncAttributeMaxDynamicSharedMemorySize, G_SMEM_BYTES);
    cudaFuncSetAttribute(flash_mma, cudaFuncAttributeMaxDynamicSharedMemorySize, F_SMEM_BYTES);

    int act4 = (Mm * Cc) / 4;
    int w4   = (Cc * Cc) / 4;

    // #1: weight conversions (fp16 single)
    CvtW5 bat;
    bat.src[0] = Wr1; bat.dst[0] = wr1;
    bat.src[1] = Wq;  bat.dst[1] = wq;
    bat.src[2] = Wk;  bat.dst[2] = wk;
    bat.src[3] = Wv;  bat.dst[3] = wv;
    bat.src[4] = Wo;  bat.dst[4] = wo;
    cvt_w_kernel<<<dim3(w4 / 256, 5), 256>>>(bat, w4);

    // #2: x -> fp16 hi/lo
    cvt_hilo16_kernel<<<act4 / 256, 256>>>(x, xh, xl, act4);

    // #3: mean partials
    mean_part_kernel<<<dim3(Cc / 256, 64, Bb), 256>>>(x);

    // #4 (profiled slot): fused r1 + Q GEMMs (both read x hi/lo)
    GJobs j1;
    j1.j[0].Ah = xh; j1.j[0].Al = xl; j1.j[0].W = wr1; j1.j[0].bias = br1;
    j1.j[0].out = r1; j1.j[0].oh = nullptr; j1.j[0].ol = nullptr;
    j1.j[0].scale = 1.0f; j1.j[0].mode = 1;
    j1.j[1].Ah = xh; j1.j[1].Al = xl; j1.j[1].W = wq; j1.j[1].bias = bq;
    j1.j[1].out = nullptr; j1.j[1].oh = qh; j1.j[1].ol = ql;
    j1.j[1].scale = ATT_SCALE; j1.j[1].mode = 2;
    gemm_multi<<<dim3(Cc / 128, Mm / 128, 2), 256, G_SMEM_BYTES>>>(j1);

    // #5: mean reduce (only needed before routing)
    mean_reduce_kernel<<<(Bb * Cc) / 256, 256>>>();

    // #6: routing -> routed fp16 hi/lo
    routing_kernel<<<Mm, 128>>>(r1, Wr2, br2, x, rth, rtl);

    // #7: fused K + V GEMMs (both read routed hi/lo)
    GJobs j2;
    j2.j[0].Ah = rth; j2.j[0].Al = rtl; j2.j[0].W = wk; j2.j[0].bias = bk;
    j2.j[0].out = nullptr; j2.j[0].oh = kf; j2.j[0].ol = nullptr;
    j2.j[0].scale = 1.0f; j2.j[0].mode = 3;
    j2.j[1].Ah = rth; j2.j[1].Al = rtl; j2.j[1].W = wv; j2.j[1].bias = bv;
    j2.j[1].out = nullptr; j2.j[1].oh = vf; j2.j[1].ol = nullptr;
    j2.j[1].scale = 1.0f; j2.j[1].mode = 3;
    gemm_multi<<<dim3(Cc / 128, Mm / 128, 2), 256, G_SMEM_BYTES>>>(j2);

    // #8: flash attention (R8 config: 64-row CTAs, 3-stage, 2/SM)
    flash_mma<<<dim3(Tt / 64, Hh, Bb), 128, F_SMEM_BYTES>>>(
        qh, ql, kf, vf, ath, atl);

    // #9: output projection (fp32 out)
    GJobs j3;
    j3.j[0].Ah = ath; j3.j[0].Al = atl; j3.j[0].W = wo; j3.j[0].bias = bo;
    j3.j[0].out = out; j3.j[0].oh = nullptr; j3.j[0].ol = nullptr;
    j3.j[0].scale = 1.0f; j3.j[0].mode = 0;
    j3.j[1] = j3.j[0];
    gemm_multi<<<dim3(Cc / 128, Mm / 128, 1), 256, G_SMEM_BYTES>>>(j3);
}

// round 12
// speedup vs baseline: 1.0714x; 1.0714x over previous
#include <cuda_runtime.h>
#include <cuda_bf16.h>
#include <cuda_fp16.h>
#include <math.h>
#include <stdint.h>

// Problem constants
#define Bb 2
#define Tt 2048
#define Cc 1024
#define Hh 16
#define Dd 64
#define Mm (Bb*Tt)           // 4096 tokens
#define ATT_SCALE 0.125f     // D^-0.5

// ---------------- scratch (device globals; no allocations allowed) ----------
__device__ float g_r1[Mm*Cc];
__device__ float g_part[64*Bb*Cc];
__device__ float g_mean[Bb*Cc];

// fp16 buffers (activations hi/lo, weights single)
__device__ __half g_xh[Mm*Cc],  g_xl[Mm*Cc];
__device__ __half g_rth[Mm*Cc], g_rtl[Mm*Cc];
__device__ __half g_ath[Mm*Cc], g_atl[Mm*Cc];
__device__ __half g_qh[Mm*Cc],  g_ql[Mm*Cc];
__device__ __half g_kf[Mm*Cc],  g_vf[Mm*Cc];
__device__ __half g_wq[Cc*Cc], g_wk[Cc*Cc], g_wv[Cc*Cc];
__device__ __half g_wo[Cc*Cc], g_wr1[Cc*Cc];

// ================= PTX helpers (sm_100 baseline ISA only) ====================
__device__ __forceinline__ uint32_t smem_u32(const void* p) {
    uint32_t a;
    asm("{ .reg .u64 t; cvta.to.shared.u64 t, %1; cvt.u32.u64 %0, t; }"
        : "=r"(a) : "l"(p));
    return a;
}
__device__ __forceinline__ void cpasync16(uint32_t dst, const void* src) {
    asm volatile("cp.async.cg.shared.global [%0], [%1], 16;" :: "r"(dst), "l"(src));
}
__device__ __forceinline__ void ldsm4(uint32_t& r0, uint32_t& r1, uint32_t& r2,
                                      uint32_t& r3, uint32_t addr) {
    asm volatile("ldmatrix.sync.aligned.m8n8.x4.shared.b16 {%0,%1,%2,%3}, [%4];"
        : "=r"(r0), "=r"(r1), "=r"(r2), "=r"(r3) : "r"(addr));
}
__device__ __forceinline__ void ldsm4t(uint32_t& r0, uint32_t& r1, uint32_t& r2,
                                       uint32_t& r3, uint32_t addr) {
    asm volatile("ldmatrix.sync.aligned.m8n8.x4.trans.shared.b16 {%0,%1,%2,%3}, [%4];"
        : "=r"(r0), "=r"(r1), "=r"(r2), "=r"(r3) : "r"(addr));
}
__device__ __forceinline__ void mma16816h(float* d, const uint32_t* a, const uint32_t* b) {
    asm volatile(
        "mma.sync.aligned.m16n8k16.row.col.f32.f16.f16.f32 "
        "{%0,%1,%2,%3}, {%4,%5,%6,%7}, {%8,%9}, {%0,%1,%2,%3};"
        : "+f"(d[0]), "+f"(d[1]), "+f"(d[2]), "+f"(d[3])
        : "r"(a[0]), "r"(a[1]), "r"(a[2]), "r"(a[3]), "r"(b[0]), "r"(b[1]));
}
__device__ __forceinline__ uint32_t pack_h2(float a, float b) {
    __half2 h = __floats2half2_rn(a, b);
    return *(uint32_t*)&h;
}
__device__ __forceinline__ float h_lo_res(float v, uint32_t pk) {
    __half2 h2 = *(__half2*)&pk;
    return v - __low2float(h2);
}
__device__ __forceinline__ float h_hi_res(float v, uint32_t pk) {
    __half2 h2 = *(__half2*)&pk;
    return v - __high2float(h2);
}

// ---------------- mean pool (deterministic two-stage) -----------------------
__global__ __launch_bounds__(256) void mean_part_kernel(const float* __restrict__ x) {
    int c  = blockIdx.x * 256 + threadIdx.x;
    int b  = blockIdx.z;
    int t0 = blockIdx.y * (Tt / 64);
    float s = 0.f;
    #pragma unroll 8
    for (int tt = 0; tt < Tt / 64; tt++)
        s += x[((size_t)b * Tt + t0 + tt) * Cc + c];
    g_part[((size_t)blockIdx.y * Bb + b) * Cc + c] = s;
}

__global__ __launch_bounds__(256) void mean_reduce_kernel() {
    int idx = blockIdx.x * 256 + threadIdx.x;
    if (idx < Bb * Cc) {
        float s = 0.f;
        #pragma unroll
        for (int u = 0; u < 64; u++) s += g_part[(size_t)u * Bb * Cc + idx];
        g_mean[idx] = s * (1.0f / (float)Tt);
    }
}

// ---------------- conversions ------------------------------------------------
__global__ __launch_bounds__(256) void cvt_hilo16_kernel(
    const float* __restrict__ x, __half* __restrict__ hi,
    __half* __restrict__ lo, int n4)
{
    int i = blockIdx.x * 256 + threadIdx.x;
    if (i >= n4) return;
    float4 v = ((const float4*)x)[i];
    uint32_t h0 = pack_h2(v.x, v.y);
    uint32_t h1 = pack_h2(v.z, v.w);
    uint2 hh; hh.x = h0; hh.y = h1;
    uint2 ll;
    ll.x = pack_h2(h_lo_res(v.x, h0), h_hi_res(v.y, h0));
    ll.y = pack_h2(h_lo_res(v.z, h1), h_hi_res(v.w, h1));
    ((uint2*)hi)[i] = hh;
    ((uint2*)lo)[i] = ll;
}

struct CvtW5 {
    const float* src[5];
    __half* dst[5];
};
__global__ __launch_bounds__(256) void cvt_w_kernel(CvtW5 b, int n4) {
    int t = blockIdx.y;
    int i = blockIdx.x * 256 + threadIdx.x;
    if (i >= n4) return;
    float4 v = ((const float4*)b.src[t])[i];
    uint2 o;
    o.x = pack_h2(v.x, v.y);
    o.y = pack_h2(v.z, v.w);
    ((uint2*)b.dst[t])[i] = o;
}

// ================= HMMA GEMM (fp16, TERMS-term) ==============================
// Y[M,N] = A[M,K] @ W[N,K]^T + bias.  TERMS=2: A = Ah + Al; TERMS=1: Ah only.
// CTA 128x128, BK=64, stage {Ah,Al,W}, 2-stage cp.async, 2 CTAs/SM.
// MODE 0: fp32; MODE 1: tanh fp32; MODE 2: fp16 hi/lo (x scale); MODE 3: fp16
#define G_NCH 16
#define G_LD 72
#define G_TILE (128 * G_LD * 2)             // 18432 bytes per tensor tile
#define G_STAGE_BYTES (3 * G_TILE)          // 55296
#define G_SMEM_BYTES (2 * G_STAGE_BYTES)    // 110592

template<int MODE, int TERMS>
__global__ __launch_bounds__(256, 2) void gemm_mma(
    const __half* __restrict__ Ah, const __half* __restrict__ Al,
    const __half* __restrict__ W,
    const float* __restrict__ bias, float* __restrict__ out,
    __half* __restrict__ outh, __half* __restrict__ outl, float scale)
{
    extern __shared__ __align__(16) uint8_t gsm[];
    uint32_t base = smem_u32(gsm);

    int tid = threadIdx.x;
    int wid = tid >> 5;
    int l   = tid & 31;
    int wm  = wid >> 1;
    int wn  = wid & 1;
    int m0  = blockIdx.y * 128;
    int n0  = blockIdx.x * 128;

    int lrow = tid >> 3;        // 0..31
    int lc16 = tid & 7;

    int arow = wm * 32 + (l & 15);
    int akc  = (l >> 4) * 8;
    int brow_in = (l & 7) + ((l >> 4) & 1) * 8;
    int bkc  = ((l >> 3) & 1) * 8;

    float acc[2][8][4];
    #pragma unroll
    for (int i = 0; i < 2; i++)
        #pragma unroll
        for (int j = 0; j < 8; j++)
            #pragma unroll
            for (int u = 0; u < 4; u++) acc[i][j][u] = 0.f;

    auto load_tile = [&](int c, int s) {
        int k0 = c * 64;
        uint32_t sb = base + s * G_STAGE_BYTES;
        #pragma unroll
        for (int it = 0; it < 4; it++) {
            int row = lrow + it * 32;
            uint32_t off = (row * G_LD + lc16 * 8) * 2;
            cpasync16(sb + off, Ah + (size_t)(m0 + row) * Cc + k0 + lc16 * 8);
            if (TERMS == 2)
                cpasync16(sb + G_TILE + off, Al + (size_t)(m0 + row) * Cc + k0 + lc16 * 8);
            cpasync16(sb + 2 * G_TILE + off, W + (size_t)(n0 + row) * Cc + k0 + lc16 * 8);
        }
    };

    load_tile(0, 0);
    asm volatile("cp.async.commit_group;");

    for (int c = 0; c < G_NCH; c++) {
        asm volatile("cp.async.wait_group 0;");
        __syncthreads();
        if (c + 1 < G_NCH) {
            load_tile(c + 1, (c + 1) & 1);
            asm volatile("cp.async.commit_group;");
        }

        uint32_t ab = base + (c & 1) * G_STAGE_BYTES;
        uint32_t lb = ab + G_TILE;
        uint32_t wb = ab + 2 * G_TILE;
        #pragma unroll
        for (int ks = 0; ks < 4; ks++) {
            uint32_t ah[2][4], al[2][4];
            #pragma unroll
            for (int i = 0; i < 2; i++) {
                uint32_t ro = ((arow + i * 16) * G_LD + akc + ks * 16) * 2;
                ldsm4(ah[i][0], ah[i][1], ah[i][2], ah[i][3], ab + ro);
                if (TERMS == 2)
                    ldsm4(al[i][0], al[i][1], al[i][2], al[i][3], lb + ro);
            }
            uint32_t wf[4][4];
            #pragma unroll
            for (int nn = 0; nn < 4; nn++)
                ldsm4(wf[nn][0], wf[nn][1], wf[nn][2], wf[nn][3],
                      wb + ((wn * 64 + nn * 16 + brow_in) * G_LD + bkc + ks * 16) * 2);
            #pragma unroll
            for (int i = 0; i < 2; i++)
                #pragma unroll
                for (int j = 0; j < 8; j++) {
                    mma16816h(acc[i][j], ah[i], &wf[j >> 1][(j & 1) * 2]);
                    if (TERMS == 2)
                        mma16816h(acc[i][j], al[i], &wf[j >> 1][(j & 1) * 2]);
                }
        }
    }

    // epilogue
    #pragma unroll
    for (int i = 0; i < 2; i++) {
        int row = m0 + wm * 32 + i * 16 + (l >> 2);
        #pragma unroll
        for (int j = 0; j < 8; j++) {
            int col = n0 + wn * 64 + j * 8 + (l & 3) * 2;
            float b0v = __ldg(&bias[col]);
            float b1v = __ldg(&bias[col + 1]);
            float v0 = acc[i][j][0] + b0v;
            float v1 = acc[i][j][1] + b1v;
            float v2 = acc[i][j][2] + b0v;
            float v3 = acc[i][j][3] + b1v;
            if (MODE == 1) {
                v0 = tanhf(v0); v1 = tanhf(v1);
                v2 = tanhf(v2); v3 = tanhf(v3);
            }
            if (MODE == 2) {
                v0 *= scale; v1 *= scale; v2 *= scale; v3 *= scale;
                uint32_t h0 = pack_h2(v0, v1);
                uint32_t h1 = pack_h2(v2, v3);
                *(uint32_t*)(outh + (size_t)row * Cc + col) = h0;
                *(uint32_t*)(outh + (size_t)(row + 8) * Cc + col) = h1;
                *(uint32_t*)(outl + (size_t)row * Cc + col) =
                    pack_h2(h_lo_res(v0, h0), h_hi_res(v1, h0));
                *(uint32_t*)(outl + (size_t)(row + 8) * Cc + col) =
                    pack_h2(h_lo_res(v2, h1), h_hi_res(v3, h1));
            } else if (MODE == 3) {
                *(uint32_t*)(outh + (size_t)row * Cc + col) = pack_h2(v0, v1);
                *(uint32_t*)(outh + (size_t)(row + 8) * Cc + col) = pack_h2(v2, v3);
            } else if (MODE != 2 && MODE != 3) {
                float2 p0; p0.x = v0; p0.y = v1;
                float2 p1; p1.x = v2; p1.y = v3;
                *(float2*)(out + (size_t)row * Cc + col) = p0;
                *(float2*)(out + (size_t)(row + 8) * Cc + col) = p1;
            }
        }
    }
}

// ---------------- routing: logits -> softmax -> routed (fp16 hi/lo) ---------
__global__ __launch_bounds__(128) void routing_kernel(
    const float* __restrict__ r1, const float* __restrict__ Wr2,
    const float* __restrict__ br2, const float* __restrict__ x,
    __half* __restrict__ rth, __half* __restrict__ rtl)
{
    int t = blockIdx.x;
    int b = t >> 11;
    int tid = threadIdx.x;

    const float* rrow = r1 + (size_t)t * Cc;
    float s0 = 0.f, s1 = 0.f, s2 = 0.f;
    for (int c = tid; c < Cc; c += 128) {
        float vv = rrow[c];
        s0 = fmaf(vv, Wr2[c],          s0);
        s1 = fmaf(vv, Wr2[Cc + c],     s1);
        s2 = fmaf(vv, Wr2[2 * Cc + c], s2);
    }
    #pragma unroll
    for (int o = 16; o; o >>= 1) {
        s0 += __shfl_xor_sync(0xffffffffu, s0, o);
        s1 += __shfl_xor_sync(0xffffffffu, s1, o);
        s2 += __shfl_xor_sync(0xffffffffu, s2, o);
    }
    __shared__ float red[3][4];
    __shared__ float wsh[2];
    if ((tid & 31) == 0) {
        red[0][tid >> 5] = s0; red[1][tid >> 5] = s1; red[2][tid >> 5] = s2;
    }
    __syncthreads();
    if (tid == 0) {
        float l0 = red[0][0] + red[0][1] + red[0][2] + red[0][3] + br2[0];
        float l1 = red[1][0] + red[1][1] + red[1][2] + red[1][3] + br2[1];
        float l2 = red[2][0] + red[2][1] + red[2][2] + red[2][3] + br2[2];
        float mx = fmaxf(l0, fmaxf(l1, l2));
        float e0 = expf(l0 - mx), e1 = expf(l1 - mx), e2 = expf(l2 - mx);
        float inv = 1.0f / (e0 + e1 + e2);
        wsh[0] = e0 * inv; wsh[1] = e1 * inv;
    }
    __syncthreads();
    float w0 = wsh[0], w1 = wsh[1];

    const float4* x4 = (const float4*)(x + (size_t)t * Cc);
    const float4* m4 = (const float4*)(g_mean + (size_t)b * Cc);
    uint2* ho = (uint2*)(rth + (size_t)t * Cc);
    uint2* lo = (uint2*)(rtl + (size_t)t * Cc);
    for (int c4 = tid; c4 < Cc / 4; c4 += 128) {
        float4 xv = x4[c4], mv = m4[c4];
        float r0 = xv.x * w0 + mv.x * w1;
        float r1v = xv.y * w0 + mv.y * w1;
        float r2 = xv.z * w0 + mv.z * w1;
        float r3 = xv.w * w0 + mv.w * w1;
        uint32_t h0 = pack_h2(r0, r1v);
        uint32_t h1 = pack_h2(r2, r3);
        uint2 hh; hh.x = h0; hh.y = h1;
        uint2 ll;
        ll.x = pack_h2(h_lo_res(r0, h0), h_hi_res(r1v, h0));
        ll.y = pack_h2(h_lo_res(r2, h1), h_hi_res(r3, h1));
        ho[c4] = hh;
        lo[c4] = ll;
    }
}

// ================= tensor-core flash attention (all fp16) ====================
// CTA: 64 Q rows (4 warps x 16), 128 threads, KV chunks of 64, 3-stage pipe.
// 2 CTAs/SM. S = Qh*K + Ql*K (fp16 2-term); PV = P x V single term.
// (exact R8 configuration — best measured)
#define F_LD 72
#define FQ_HALVES (64 * F_LD)
#define FS_HALVES (64 * F_LD)
#define F_TSTAGE (2 * FS_HALVES)            // K, V
#define F_STAGE0 (2 * FQ_HALVES)
#define F_SMEM_BYTES ((2 * FQ_HALVES + 3 * F_TSTAGE) * 2)   // 73728

__global__ __launch_bounds__(128, 2) void flash_mma(
    const __half* __restrict__ qhp, const __half* __restrict__ qlp,
    const __half* __restrict__ kf, const __half* __restrict__ vf,
    __half* __restrict__ oh, __half* __restrict__ ol)
{
    extern __shared__ __half fsh[];
    uint32_t fsb = smem_u32(fsh);

    int tid = threadIdx.x;
    int w   = tid >> 5;            // 0..3
    int l   = tid & 31;
    int q0  = blockIdx.x * 64;
    int h   = blockIdx.y;
    int b   = blockIdx.z;
    int tokb = b * Tt;
    int hoff = h * Dd;

    // ---- load Q (hi+lo), rides with chunk-0's commit group ----
    {
        const __half* srcs[2] = {qhp, qlp};
        #pragma unroll
        for (int ten = 0; ten < 2; ten++) {
            #pragma unroll
            for (int it = 0; it < 4; it++) {
                int idx = tid + it * 128;          // [0,512)
                int row = idx >> 3, c16 = idx & 7;
                uint32_t dst = fsb + ((ten * FQ_HALVES) + row * F_LD + c16 * 8) * 2;
                cpasync16(dst, srcs[ten] + (size_t)(tokb + q0 + row) * Cc + hoff + c16 * 8);
            }
        }
    }
    auto load_kv = [&](int c, int s) {
        int kt0 = c * 64;
        uint32_t sb = fsb + (F_STAGE0 + s * F_TSTAGE) * 2;
        #pragma unroll
        for (int it = 0; it < 4; it++) {
            int idx = tid + it * 128;              // [0,512)
            int row = idx >> 3, c16 = idx & 7;
            uint32_t off = (row * F_LD + c16 * 8) * 2;
            cpasync16(sb + off, kf + (size_t)(tokb + kt0 + row) * Cc + hoff + c16 * 8);
            cpasync16(sb + FS_HALVES * 2 + off,
                      vf + (size_t)(tokb + kt0 + row) * Cc + hoff + c16 * 8);
        }
    };

    load_kv(0, 0);
    asm volatile("cp.async.commit_group;");
    load_kv(1, 1);
    asm volatile("cp.async.commit_group;");

    int arow = (l & 15);
    int akc  = (l >> 4) * 8;
    int brow_in = (l & 7) + ((l >> 4) & 1) * 8;
    int bkc  = ((l >> 3) & 1) * 8;
    int vrow = (l & 7) + ((l >> 3) & 1) * 8;
    int vcol = ((l >> 4) & 1) * 8;

    uint32_t qh[4][4], ql[4][4];
    float oacc[8][4];
    #pragma unroll
    for (int j = 0; j < 8; j++)
        #pragma unroll
        for (int u = 0; u < 4; u++) oacc[j][u] = 0.f;
    float m0r = -1e30f, m1r = -1e30f, l0r = 0.f, l1r = 0.f;

    const int NCH = Tt / 64;
    for (int c = 0; c < NCH; c++) {
        if (c < NCH - 1) asm volatile("cp.async.wait_group 1;");
        else             asm volatile("cp.async.wait_group 0;");
        __syncthreads();

        if (c == 0) {
            #pragma unroll
            for (int kt = 0; kt < 4; kt++) {
                ldsm4(qh[kt][0], qh[kt][1], qh[kt][2], qh[kt][3],
                      fsb + ((w * 16 + arow) * F_LD + kt * 16 + akc) * 2);
                ldsm4(ql[kt][0], ql[kt][1], ql[kt][2], ql[kt][3],
                      fsb + (FQ_HALVES + (w * 16 + arow) * F_LD + kt * 16 + akc) * 2);
            }
        }

        if (c + 2 < NCH) {
            load_kv(c + 2, (c + 2) % 3);
            asm volatile("cp.async.commit_group;");
        }

        uint32_t SB = F_STAGE0 + (c % 3) * F_TSTAGE;
        uint32_t KF = SB, VF = SB + FS_HALVES;

        // ---- S = Q K^T (fp16 2-term) ----
        float sacc[8][4];
        #pragma unroll
        for (int j = 0; j < 8; j++)
            #pragma unroll
            for (int u = 0; u < 4; u++) sacc[j][u] = 0.f;

        #pragma unroll
        for (int ks = 0; ks < 4; ks++) {
            uint32_t kh[4][4];
            #pragma unroll
            for (int g = 0; g < 4; g++) {
                uint32_t ro = ((g * 16 + brow_in) * F_LD + bkc + ks * 16) * 2;
                ldsm4(kh[g][0], kh[g][1], kh[g][2], kh[g][3], fsb + KF * 2 + ro);
            }
            #pragma unroll
            for (int g = 0; g < 4; g++)
                #pragma unroll
                for (int sub = 0; sub < 2; sub++) {
                    int j = g * 2 + sub;
                    mma16816h(sacc[j], qh[ks], &kh[g][sub * 2]);
                    mma16816h(sacc[j], ql[ks], &kh[g][sub * 2]);
                }
        }

        // ---- online softmax, P packed fp16 ----
        float mx0 = -1e30f, mx1 = -1e30f;
        #pragma unroll
        for (int j = 0; j < 8; j++) {
            mx0 = fmaxf(mx0, fmaxf(sacc[j][0], sacc[j][1]));
            mx1 = fmaxf(mx1, fmaxf(sacc[j][2], sacc[j][3]));
        }
        mx0 = fmaxf(mx0, __shfl_xor_sync(0xffffffffu, mx0, 1));
        mx0 = fmaxf(mx0, __shfl_xor_sync(0xffffffffu, mx0, 2));
        mx1 = fmaxf(mx1, __shfl_xor_sync(0xffffffffu, mx1, 1));
        mx1 = fmaxf(mx1, __shfl_xor_sync(0xffffffffu, mx1, 2));
        float mn0 = fmaxf(m0r, mx0), mn1 = fmaxf(m1r, mx1);
        float cor0 = __expf(m0r - mn0), cor1 = __expf(m1r - mn1);
        m0r = mn0; m1r = mn1;

        uint32_t phf[4][4];
        float rs0 = 0.f, rs1 = 0.f;
        #pragma unroll
        for (int j = 0; j < 8; j++) {
            float e0 = __expf(sacc[j][0] - mn0);
            float e1 = __expf(sacc[j][1] - mn0);
            float e2 = __expf(sacc[j][2] - mn1);
            float e3 = __expf(sacc[j][3] - mn1);
            rs0 += e0 + e1; rs1 += e2 + e3;
            int kt = j >> 1, sl = (j & 1) * 2;
            phf[kt][sl]     = pack_h2(e0, e1);
            phf[kt][sl + 1] = pack_h2(e2, e3);
        }
        rs0 += __shfl_xor_sync(0xffffffffu, rs0, 1);
        rs0 += __shfl_xor_sync(0xffffffffu, rs0, 2);
        rs1 += __shfl_xor_sync(0xffffffffu, rs1, 1);
        rs1 += __shfl_xor_sync(0xffffffffu, rs1, 2);
        l0r = l0r * cor0 + rs0;
        l1r = l1r * cor1 + rs1;
        #pragma unroll
        for (int j = 0; j < 8; j++) {
            oacc[j][0] *= cor0; oacc[j][1] *= cor0;
            oacc[j][2] *= cor1; oacc[j][3] *= cor1;
        }

        // ---- O += P V (fp16, single term) ----
        #pragma unroll
        for (int kt = 0; kt < 4; kt++) {
            #pragma unroll
            for (int dg = 0; dg < 4; dg++) {
                uint32_t vh[4];
                uint32_t ro = ((kt * 16 + vrow) * F_LD + dg * 16 + vcol) * 2;
                ldsm4t(vh[0], vh[1], vh[2], vh[3], fsb + VF * 2 + ro);
                #pragma unroll
                for (int sub = 0; sub < 2; sub++)
                    mma16816h(oacc[dg * 2 + sub], phf[kt], &vh[sub * 2]);
            }
        }
    }

    // ---- epilogue: normalize, fp16 hi/lo split, write ----
    float inv0 = 1.0f / l0r, inv1 = 1.0f / l1r;
    int row0 = tokb + q0 + w * 16 + (l >> 2);
    int row1 = row0 + 8;
    #pragma unroll
    for (int dt = 0; dt < 8; dt++) {
        int col = hoff + dt * 8 + (l & 3) * 2;
        float v0 = oacc[dt][0] * inv0, v1 = oacc[dt][1] * inv0;
        float v2 = oacc[dt][2] * inv1, v3 = oacc[dt][3] * inv1;
        uint32_t h0 = pack_h2(v0, v1);
        uint32_t h1 = pack_h2(v2, v3);
        *(uint32_t*)(oh + (size_t)row0 * Cc + col) = h0;
        *(uint32_t*)(oh + (size_t)row1 * Cc + col) = h1;
        *(uint32_t*)(ol + (size_t)row0 * Cc + col) =
            pack_h2(h_lo_res(v0, h0), h_hi_res(v1, h0));
        *(uint32_t*)(ol + (size_t)row1 * Cc + col) =
            pack_h2(h_lo_res(v2, h1), h_hi_res(v3, h1));
    }
}

// ---------------- host driver -----------------------------------------------
extern "C" void kernel_launch(void* const* d_in, const int* in_sizes, int n_in,
                              void* d_out, int out_size)
{
    const float* x   = (const float*)d_in[0];
    const float* Wq  = (const float*)d_in[1];
    const float* bq  = (const float*)d_in[2];
    const float* Wk  = (const float*)d_in[3];
    const float* bk  = (const float*)d_in[4];
    const float* Wv  = (const float*)d_in[5];
    const float* bv  = (const float*)d_in[6];
    const float* Wo  = (const float*)d_in[7];
    const float* bo  = (const float*)d_in[8];
    const float* Wr1 = (const float*)d_in[9];
    const float* br1 = (const float*)d_in[10];
    const float* Wr2 = (const float*)d_in[11];
    const float* br2 = (const float*)d_in[12];
    float* out = (float*)d_out;

    float* r1;
    cudaGetSymbolAddress((void**)&r1, g_r1);

    __half *xh, *xl, *rth, *rtl, *ath, *atl, *qh, *ql, *kf, *vf;
    __half *wq, *wk, *wv, *wo, *wr1;
    cudaGetSymbolAddress((void**)&xh,  g_xh);  cudaGetSymbolAddress((void**)&xl,  g_xl);
    cudaGetSymbolAddress((void**)&rth, g_rth); cudaGetSymbolAddress((void**)&rtl, g_rtl);
    cudaGetSymbolAddress((void**)&ath, g_ath); cudaGetSymbolAddress((void**)&atl, g_atl);
    cudaGetSymbolAddress((void**)&qh,  g_qh);  cudaGetSymbolAddress((void**)&ql,  g_ql);
    cudaGetSymbolAddress((void**)&kf,  g_kf);  cudaGetSymbolAddress((void**)&vf,  g_vf);
    cudaGetSymbolAddress((void**)&wq,  g_wq);  cudaGetSymbolAddress((void**)&wk,  g_wk);
    cudaGetSymbolAddress((void**)&wv,  g_wv);  cudaGetSymbolAddress((void**)&wo,  g_wo);
    cudaGetSymbolAddress((void**)&wr1, g_wr1);

    cudaFuncSetAttribute((gemm_mma<0,2>), cudaFuncAttributeMaxDynamicSharedMemorySize, G_SMEM_BYTES);
    cudaFuncSetAttribute((gemm_mma<1,1>), cudaFuncAttributeMaxDynamicSharedMemorySize, G_SMEM_BYTES);
    cudaFuncSetAttribute((gemm_mma<2,2>), cudaFuncAttributeMaxDynamicSharedMemorySize, G_SMEM_BYTES);
    cudaFuncSetAttribute((gemm_mma<3,2>), cudaFuncAttributeMaxDynamicSharedMemorySize, G_SMEM_BYTES);
    cudaFuncSetAttribute(flash_mma, cudaFuncAttributeMaxDynamicSharedMemorySize, F_SMEM_BYTES);

    dim3 gemm_grid(Cc / 128, Mm / 128);   // (8, 32)
    int act4 = (Mm * Cc) / 4;
    int w4   = (Cc * Cc) / 4;

    // #1: weight conversions (fp16 single)
    CvtW5 bat;
    bat.src[0] = Wr1; bat.dst[0] = wr1;
    bat.src[1] = Wq;  bat.dst[1] = wq;
    bat.src[2] = Wk;  bat.dst[2] = wk;
    bat.src[3] = Wv;  bat.dst[3] = wv;
    bat.src[4] = Wo;  bat.dst[4] = wo;
    cvt_w_kernel<<<dim3(w4 / 256, 5), 256>>>(bat, w4);

    // #2: x -> fp16 hi/lo
    cvt_hilo16_kernel<<<act4 / 256, 256>>>(x, xh, xl, act4);

    // #3: mean partials
    mean_part_kernel<<<dim3(Cc / 256, 64, Bb), 256>>>(x);

    // #4 (profiled slot): r1 = tanh(x @ Wr1^T + br1), SINGLE fp16 term
    gemm_mma<1,1><<<gemm_grid, 256, G_SMEM_BYTES>>>(xh, xl, wr1, br1, r1,
                                                    nullptr, nullptr, 1.0f);

    // #5: Q (pre-scaled, fp16 hi/lo out), 2-term
    gemm_mma<2,2><<<gemm_grid, 256, G_SMEM_BYTES>>>(xh, xl, wq, bq, nullptr,
                                                    qh, ql, ATT_SCALE);

    // #6: mean reduce
    mean_reduce_kernel<<<(Bb * Cc) / 256, 256>>>();

    // #7: routing -> routed fp16 hi/lo
    routing_kernel<<<Mm, 128>>>(r1, Wr2, br2, x, rth, rtl);

    // #8, #9: K, V (fp16 single out), 2-term
    gemm_mma<3,2><<<gemm_grid, 256, G_SMEM_BYTES>>>(rth, rtl, wk, bk, nullptr,
                                                    kf, nullptr, 1.0f);
    gemm_mma<3,2><<<gemm_grid, 256, G_SMEM_BYTES>>>(rth, rtl, wv, bv, nullptr,
                                                    vf, nullptr, 1.0f);

    // #10: flash attention (R8 config)
    flash_mma<<<dim3(Tt / 64, Hh, Bb), 128, F_SMEM_BYTES>>>(
        qh, ql, kf, vf, ath, atl);

    // #11: output projection (fp32 out), 2-term
    gemm_mma<0,2><<<gemm_grid, 256, G_SMEM_BYTES>>>(ath, atl, wo, bo, out,
                                                    nullptr, nullptr, 1.0f);
}

// round 13
// speedup vs baseline: 1.3260x; 1.2377x over previous
#include <cuda_runtime.h>
#include <cuda_bf16.h>
#include <cuda_fp16.h>
#include <math.h>
#include <stdint.h>

// Problem constants
#define Bb 2
#define Tt 2048
#define Cc 1024
#define Hh 16
#define Dd 64
#define Mm (Bb*Tt)           // 4096 tokens
#define ATT_SCALE 0.125f     // D^-0.5

// ---------------- scratch (device globals; no allocations allowed) ----------
__device__ float g_r1[Mm*Cc];
__device__ float g_part[64*Bb*Cc];
__device__ float g_mean[Bb*Cc];

// fp16 buffers
__device__ __half g_xf[Mm*Cc];                  // x single fp16
__device__ __half g_rtf[Mm*Cc];                 // routed single fp16
__device__ __half g_ath[Mm*Cc], g_atl[Mm*Cc];   // att hi/lo (O proj stays 2-term)
__device__ __half g_qf[Mm*Cc];                  // Q single fp16 (pre-scaled)
__device__ __half g_kf[Mm*Cc],  g_vf[Mm*Cc];
__device__ __half g_wq[Cc*Cc], g_wk[Cc*Cc], g_wv[Cc*Cc];
__device__ __half g_wo[Cc*Cc], g_wr1[Cc*Cc];

// ================= PTX helpers (sm_100 baseline ISA only) ====================
__device__ __forceinline__ uint32_t smem_u32(const void* p) {
    uint32_t a;
    asm("{ .reg .u64 t; cvta.to.shared.u64 t, %1; cvt.u32.u64 %0, t; }"
        : "=r"(a) : "l"(p));
    return a;
}
__device__ __forceinline__ void cpasync16(uint32_t dst, const void* src) {
    asm volatile("cp.async.cg.shared.global [%0], [%1], 16;" :: "r"(dst), "l"(src));
}
__device__ __forceinline__ void ldsm4(uint32_t& r0, uint32_t& r1, uint32_t& r2,
                                      uint32_t& r3, uint32_t addr) {
    asm volatile("ldmatrix.sync.aligned.m8n8.x4.shared.b16 {%0,%1,%2,%3}, [%4];"
        : "=r"(r0), "=r"(r1), "=r"(r2), "=r"(r3) : "r"(addr));
}
__device__ __forceinline__ void ldsm4t(uint32_t& r0, uint32_t& r1, uint32_t& r2,
                                       uint32_t& r3, uint32_t addr) {
    asm volatile("ldmatrix.sync.aligned.m8n8.x4.trans.shared.b16 {%0,%1,%2,%3}, [%4];"
        : "=r"(r0), "=r"(r1), "=r"(r2), "=r"(r3) : "r"(addr));
}
__device__ __forceinline__ void mma16816h(float* d, const uint32_t* a, const uint32_t* b) {
    asm volatile(
        "mma.sync.aligned.m16n8k16.row.col.f32.f16.f16.f32 "
        "{%0,%1,%2,%3}, {%4,%5,%6,%7}, {%8,%9}, {%0,%1,%2,%3};"
        : "+f"(d[0]), "+f"(d[1]), "+f"(d[2]), "+f"(d[3])
        : "r"(a[0]), "r"(a[1]), "r"(a[2]), "r"(a[3]), "r"(b[0]), "r"(b[1]));
}
__device__ __forceinline__ uint32_t pack_h2(float a, float b) {
    __half2 h = __floats2half2_rn(a, b);
    return *(uint32_t*)&h;
}
__device__ __forceinline__ float h_lo_res(float v, uint32_t pk) {
    __half2 h2 = *(__half2*)&pk;
    return v - __low2float(h2);
}
__device__ __forceinline__ float h_hi_res(float v, uint32_t pk) {
    __half2 h2 = *(__half2*)&pk;
    return v - __high2float(h2);
}

// ---------------- mean pool (deterministic two-stage) -----------------------
__global__ __launch_bounds__(256) void mean_part_kernel(const float* __restrict__ x) {
    int c  = blockIdx.x * 256 + threadIdx.x;
    int b  = blockIdx.z;
    int t0 = blockIdx.y * (Tt / 64);
    float s = 0.f;
    #pragma unroll 8
    for (int tt = 0; tt < Tt / 64; tt++)
        s += x[((size_t)b * Tt + t0 + tt) * Cc + c];
    g_part[((size_t)blockIdx.y * Bb + b) * Cc + c] = s;
}

__global__ __launch_bounds__(256) void mean_reduce_kernel() {
    int idx = blockIdx.x * 256 + threadIdx.x;
    if (idx < Bb * Cc) {
        float s = 0.f;
        #pragma unroll
        for (int u = 0; u < 64; u++) s += g_part[(size_t)u * Bb * Cc + idx];
        g_mean[idx] = s * (1.0f / (float)Tt);
    }
}

// ---------------- conversions ------------------------------------------------
__global__ __launch_bounds__(256) void cvt16_kernel(
    const float* __restrict__ x, __half* __restrict__ o, int n4)
{
    int i = blockIdx.x * 256 + threadIdx.x;
    if (i >= n4) return;
    float4 v = ((const float4*)x)[i];
    uint2 p;
    p.x = pack_h2(v.x, v.y);
    p.y = pack_h2(v.z, v.w);
    ((uint2*)o)[i] = p;
}

struct CvtW5 {
    const float* src[5];
    __half* dst[5];
};
__global__ __launch_bounds__(256) void cvt_w_kernel(CvtW5 b, int n4) {
    int t = blockIdx.y;
    int i = blockIdx.x * 256 + threadIdx.x;
    if (i >= n4) return;
    float4 v = ((const float4*)b.src[t])[i];
    uint2 o;
    o.x = pack_h2(v.x, v.y);
    o.y = pack_h2(v.z, v.w);
    ((uint2*)b.dst[t])[i] = o;
}

// ================= HMMA GEMM (fp16, TERMS-term) ==============================
// Y[M,N] = A[M,K] @ W[N,K]^T + bias.  TERMS=2: A = Ah + Al; TERMS=1: Ah only.
// CTA 128x128, BK=64, stage {Ah,Al,W}, 2-stage cp.async, 2 CTAs/SM.
// MODE 0: fp32; MODE 1: tanh fp32; MODE 3: fp16 single (x scale)
#define G_NCH 16
#define G_LD 72
#define G_TILE (128 * G_LD * 2)             // 18432 bytes per tensor tile
#define G_STAGE_BYTES (3 * G_TILE)          // 55296
#define G_SMEM_BYTES (2 * G_STAGE_BYTES)    // 110592

template<int MODE, int TERMS>
__global__ __launch_bounds__(256, 2) void gemm_mma(
    const __half* __restrict__ Ah, const __half* __restrict__ Al,
    const __half* __restrict__ W,
    const float* __restrict__ bias, float* __restrict__ out,
    __half* __restrict__ outh, float scale)
{
    extern __shared__ __align__(16) uint8_t gsm[];
    uint32_t base = smem_u32(gsm);

    int tid = threadIdx.x;
    int wid = tid >> 5;
    int l   = tid & 31;
    int wm  = wid >> 1;
    int wn  = wid & 1;
    int m0  = blockIdx.y * 128;
    int n0  = blockIdx.x * 128;

    int lrow = tid >> 3;        // 0..31
    int lc16 = tid & 7;

    int arow = wm * 32 + (l & 15);
    int akc  = (l >> 4) * 8;
    int brow_in = (l & 7) + ((l >> 4) & 1) * 8;
    int bkc  = ((l >> 3) & 1) * 8;

    float acc[2][8][4];
    #pragma unroll
    for (int i = 0; i < 2; i++)
        #pragma unroll
        for (int j = 0; j < 8; j++)
            #pragma unroll
            for (int u = 0; u < 4; u++) acc[i][j][u] = 0.f;

    auto load_tile = [&](int c, int s) {
        int k0 = c * 64;
        uint32_t sb = base + s * G_STAGE_BYTES;
        #pragma unroll
        for (int it = 0; it < 4; it++) {
            int row = lrow + it * 32;
            uint32_t off = (row * G_LD + lc16 * 8) * 2;
            cpasync16(sb + off, Ah + (size_t)(m0 + row) * Cc + k0 + lc16 * 8);
            if (TERMS == 2)
                cpasync16(sb + G_TILE + off, Al + (size_t)(m0 + row) * Cc + k0 + lc16 * 8);
            cpasync16(sb + 2 * G_TILE + off, W + (size_t)(n0 + row) * Cc + k0 + lc16 * 8);
        }
    };

    load_tile(0, 0);
    asm volatile("cp.async.commit_group;");

    for (int c = 0; c < G_NCH; c++) {
        asm volatile("cp.async.wait_group 0;");
        __syncthreads();
        if (c + 1 < G_NCH) {
            load_tile(c + 1, (c + 1) & 1);
            asm volatile("cp.async.commit_group;");
        }

        uint32_t ab = base + (c & 1) * G_STAGE_BYTES;
        uint32_t lb = ab + G_TILE;
        uint32_t wb = ab + 2 * G_TILE;
        #pragma unroll
        for (int ks = 0; ks < 4; ks++) {
            uint32_t ah[2][4], al[2][4];
            #pragma unroll
            for (int i = 0; i < 2; i++) {
                uint32_t ro = ((arow + i * 16) * G_LD + akc + ks * 16) * 2;
                ldsm4(ah[i][0], ah[i][1], ah[i][2], ah[i][3], ab + ro);
                if (TERMS == 2)
                    ldsm4(al[i][0], al[i][1], al[i][2], al[i][3], lb + ro);
            }
            uint32_t wf[4][4];
            #pragma unroll
            for (int nn = 0; nn < 4; nn++)
                ldsm4(wf[nn][0], wf[nn][1], wf[nn][2], wf[nn][3],
                      wb + ((wn * 64 + nn * 16 + brow_in) * G_LD + bkc + ks * 16) * 2);
            #pragma unroll
            for (int i = 0; i < 2; i++)
                #pragma unroll
                for (int j = 0; j < 8; j++) {
                    mma16816h(acc[i][j], ah[i], &wf[j >> 1][(j & 1) * 2]);
                    if (TERMS == 2)
                        mma16816h(acc[i][j], al[i], &wf[j >> 1][(j & 1) * 2]);
                }
        }
    }

    // epilogue
    #pragma unroll
    for (int i = 0; i < 2; i++) {
        int row = m0 + wm * 32 + i * 16 + (l >> 2);
        #pragma unroll
        for (int j = 0; j < 8; j++) {
            int col = n0 + wn * 64 + j * 8 + (l & 3) * 2;
            float b0v = __ldg(&bias[col]);
            float b1v = __ldg(&bias[col + 1]);
            float v0 = acc[i][j][0] + b0v;
            float v1 = acc[i][j][1] + b1v;
            float v2 = acc[i][j][2] + b0v;
            float v3 = acc[i][j][3] + b1v;
            if (MODE == 1) {
                v0 = tanhf(v0); v1 = tanhf(v1);
                v2 = tanhf(v2); v3 = tanhf(v3);
            }
            if (MODE == 3) {
                v0 *= scale; v1 *= scale; v2 *= scale; v3 *= scale;
                *(uint32_t*)(outh + (size_t)row * Cc + col) = pack_h2(v0, v1);
                *(uint32_t*)(outh + (size_t)(row + 8) * Cc + col) = pack_h2(v2, v3);
            } else {
                float2 p0; p0.x = v0; p0.y = v1;
                float2 p1; p1.x = v2; p1.y = v3;
                *(float2*)(out + (size_t)row * Cc + col) = p0;
                *(float2*)(out + (size_t)(row + 8) * Cc + col) = p1;
            }
        }
    }
}

// ---------------- routing: logits -> softmax -> routed (fp16 single) --------
__global__ __launch_bounds__(128) void routing_kernel(
    const float* __restrict__ r1, const float* __restrict__ Wr2,
    const float* __restrict__ br2, const float* __restrict__ x,
    __half* __restrict__ rtf)
{
    int t = blockIdx.x;
    int b = t >> 11;
    int tid = threadIdx.x;

    const float* rrow = r1 + (size_t)t * Cc;
    float s0 = 0.f, s1 = 0.f, s2 = 0.f;
    for (int c = tid; c < Cc; c += 128) {
        float vv = rrow[c];
        s0 = fmaf(vv, Wr2[c],          s0);
        s1 = fmaf(vv, Wr2[Cc + c],     s1);
        s2 = fmaf(vv, Wr2[2 * Cc + c], s2);
    }
    #pragma unroll
    for (int o = 16; o; o >>= 1) {
        s0 += __shfl_xor_sync(0xffffffffu, s0, o);
        s1 += __shfl_xor_sync(0xffffffffu, s1, o);
        s2 += __shfl_xor_sync(0xffffffffu, s2, o);
    }
    __shared__ float red[3][4];
    __shared__ float wsh[2];
    if ((tid & 31) == 0) {
        red[0][tid >> 5] = s0; red[1][tid >> 5] = s1; red[2][tid >> 5] = s2;
    }
    __syncthreads();
    if (tid == 0) {
        float l0 = red[0][0] + red[0][1] + red[0][2] + red[0][3] + br2[0];
        float l1 = red[1][0] + red[1][1] + red[1][2] + red[1][3] + br2[1];
        float l2 = red[2][0] + red[2][1] + red[2][2] + red[2][3] + br2[2];
        float mx = fmaxf(l0, fmaxf(l1, l2));
        float e0 = expf(l0 - mx), e1 = expf(l1 - mx), e2 = expf(l2 - mx);
        float inv = 1.0f / (e0 + e1 + e2);
        wsh[0] = e0 * inv; wsh[1] = e1 * inv;
    }
    __syncthreads();
    float w0 = wsh[0], w1 = wsh[1];

    const float4* x4 = (const float4*)(x + (size_t)t * Cc);
    const float4* m4 = (const float4*)(g_mean + (size_t)b * Cc);
    uint2* ho = (uint2*)(rtf + (size_t)t * Cc);
    for (int c4 = tid; c4 < Cc / 4; c4 += 128) {
        float4 xv = x4[c4], mv = m4[c4];
        float r0 = xv.x * w0 + mv.x * w1;
        float r1v = xv.y * w0 + mv.y * w1;
        float r2 = xv.z * w0 + mv.z * w1;
        float r3 = xv.w * w0 + mv.w * w1;
        uint2 hh;
        hh.x = pack_h2(r0, r1v);
        hh.y = pack_h2(r2, r3);
        ho[c4] = hh;
    }
}

// ================= tensor-core flash attention (all fp16, 1-term S) =========
// CTA: 64 Q rows (4 warps x 16), 128 threads, KV chunks of 64, 3-stage pipe.
// 2 CTAs/SM. S = Q*K (single term); PV = P x V single term.
#define F_LD 72
#define FQ_HALVES (64 * F_LD)
#define FS_HALVES (64 * F_LD)
#define F_TSTAGE (2 * FS_HALVES)            // K, V
#define F_STAGE0 (FQ_HALVES)                // single Q tensor
#define F_SMEM_BYTES ((FQ_HALVES + 3 * F_TSTAGE) * 2)   // 64512

__global__ __launch_bounds__(128, 2) void flash_mma(
    const __half* __restrict__ qf,
    const __half* __restrict__ kf, const __half* __restrict__ vf,
    __half* __restrict__ oh, __half* __restrict__ ol)
{
    extern __shared__ __half fsh[];
    uint32_t fsb = smem_u32(fsh);

    int tid = threadIdx.x;
    int w   = tid >> 5;            // 0..3
    int l   = tid & 31;
    int q0  = blockIdx.x * 64;
    int h   = blockIdx.y;
    int b   = blockIdx.z;
    int tokb = b * Tt;
    int hoff = h * Dd;

    // ---- load Q, rides with chunk-0's commit group ----
    #pragma unroll
    for (int it = 0; it < 4; it++) {
        int idx = tid + it * 128;          // [0,512)
        int row = idx >> 3, c16 = idx & 7;
        uint32_t dst = fsb + (row * F_LD + c16 * 8) * 2;
        cpasync16(dst, qf + (size_t)(tokb + q0 + row) * Cc + hoff + c16 * 8);
    }
    auto load_kv = [&](int c, int s) {
        int kt0 = c * 64;
        uint32_t sb = fsb + (F_STAGE0 + s * F_TSTAGE) * 2;
        #pragma unroll
        for (int it = 0; it < 4; it++) {
            int idx = tid + it * 128;              // [0,512)
            int row = idx >> 3, c16 = idx & 7;
            uint32_t off = (row * F_LD + c16 * 8) * 2;
            cpasync16(sb + off, kf + (size_t)(tokb + kt0 + row) * Cc + hoff + c16 * 8);
            cpasync16(sb + FS_HALVES * 2 + off,
                      vf + (size_t)(tokb + kt0 + row) * Cc + hoff + c16 * 8);
        }
    };

    load_kv(0, 0);
    asm volatile("cp.async.commit_group;");
    load_kv(1, 1);
    asm volatile("cp.async.commit_group;");

    int arow = (l & 15);
    int akc  = (l >> 4) * 8;
    int brow_in = (l & 7) + ((l >> 4) & 1) * 8;
    int bkc  = ((l >> 3) & 1) * 8;
    int vrow = (l & 7) + ((l >> 3) & 1) * 8;
    int vcol = ((l >> 4) & 1) * 8;

    uint32_t qh[4][4];
    float oacc[8][4];
    #pragma unroll
    for (int j = 0; j < 8; j++)
        #pragma unroll
        for (int u = 0; u < 4; u++) oacc[j][u] = 0.f;
    float m0r = -1e30f, m1r = -1e30f, l0r = 0.f, l1r = 0.f;

    const int NCH = Tt / 64;
    for (int c = 0; c < NCH; c++) {
        if (c < NCH - 1) asm volatile("cp.async.wait_group 1;");
        else             asm volatile("cp.async.wait_group 0;");
        __syncthreads();

        if (c == 0) {
            #pragma unroll
            for (int kt = 0; kt < 4; kt++)
                ldsm4(qh[kt][0], qh[kt][1], qh[kt][2], qh[kt][3],
                      fsb + ((w * 16 + arow) * F_LD + kt * 16 + akc) * 2);
        }

        if (c + 2 < NCH) {
            load_kv(c + 2, (c + 2) % 3);
            asm volatile("cp.async.commit_group;");
        }

        uint32_t SB = F_STAGE0 + (c % 3) * F_TSTAGE;
        uint32_t KF = SB, VF = SB + FS_HALVES;

        // ---- S = Q K^T (single term) ----
        float sacc[8][4];
        #pragma unroll
        for (int j = 0; j < 8; j++)
            #pragma unroll
            for (int u = 0; u < 4; u++) sacc[j][u] = 0.f;

        #pragma unroll
        for (int ks = 0; ks < 4; ks++) {
            uint32_t kh[4][4];
            #pragma unroll
            for (int g = 0; g < 4; g++) {
                uint32_t ro = ((g * 16 + brow_in) * F_LD + bkc + ks * 16) * 2;
                ldsm4(kh[g][0], kh[g][1], kh[g][2], kh[g][3], fsb + KF * 2 + ro);
            }
            #pragma unroll
            for (int g = 0; g < 4; g++)
                #pragma unroll
                for (int sub = 0; sub < 2; sub++)
                    mma16816h(sacc[g * 2 + sub], qh[ks], &kh[g][sub * 2]);
        }

        // ---- online softmax, P packed fp16 ----
        float mx0 = -1e30f, mx1 = -1e30f;
        #pragma unroll
        for (int j = 0; j < 8; j++) {
            mx0 = fmaxf(mx0, fmaxf(sacc[j][0], sacc[j][1]));
            mx1 = fmaxf(mx1, fmaxf(sacc[j][2], sacc[j][3]));
        }
        mx0 = fmaxf(mx0, __shfl_xor_sync(0xffffffffu, mx0, 1));
        mx0 = fmaxf(mx0, __shfl_xor_sync(0xffffffffu, mx0, 2));
        mx1 = fmaxf(mx1, __shfl_xor_sync(0xffffffffu, mx1, 1));
        mx1 = fmaxf(mx1, __shfl_xor_sync(0xffffffffu, mx1, 2));
        float mn0 = fmaxf(m0r, mx0), mn1 = fmaxf(m1r, mx1);
        float cor0 = __expf(m0r - mn0), cor1 = __expf(m1r - mn1);
        m0r = mn0; m1r = mn1;

        uint32_t phf[4][4];
        float rs0 = 0.f, rs1 = 0.f;
        #pragma unroll
        for (int j = 0; j < 8; j++) {
            float e0 = __expf(sacc[j][0] - mn0);
            float e1 = __expf(sacc[j][1] - mn0);
            float e2 = __expf(sacc[j][2] - mn1);
            float e3 = __expf(sacc[j][3] - mn1);
            rs0 += e0 + e1; rs1 += e2 + e3;
            int kt = j >> 1, sl = (j & 1) * 2;
            phf[kt][sl]     = pack_h2(e0, e1);
            phf[kt][sl + 1] = pack_h2(e2, e3);
        }
        rs0 += __shfl_xor_sync(0xffffffffu, rs0, 1);
        rs0 += __shfl_xor_sync(0xffffffffu, rs0, 2);
        rs1 += __shfl_xor_sync(0xffffffffu, rs1, 1);
        rs1 += __shfl_xor_sync(0xffffffffu, rs1, 2);
        l0r = l0r * cor0 + rs0;
        l1r = l1r * cor1 + rs1;
        #pragma unroll
        for (int j = 0; j < 8; j++) {
            oacc[j][0] *= cor0; oacc[j][1] *= cor0;
            oacc[j][2] *= cor1; oacc[j][3] *= cor1;
        }

        // ---- O += P V (fp16, single term) ----
        #pragma unroll
        for (int kt = 0; kt < 4; kt++) {
            #pragma unroll
            for (int dg = 0; dg < 4; dg++) {
                uint32_t vh[4];
                uint32_t ro = ((kt * 16 + vrow) * F_LD + dg * 16 + vcol) * 2;
                ldsm4t(vh[0], vh[1], vh[2], vh[3], fsb + VF * 2 + ro);
                #pragma unroll
                for (int sub = 0; sub < 2; sub++)
                    mma16816h(oacc[dg * 2 + sub], phf[kt], &vh[sub * 2]);
            }
        }
    }

    // ---- epilogue: normalize, fp16 hi/lo split, write (O proj is 2-term) ----
    float inv0 = 1.0f / l0r, inv1 = 1.0f / l1r;
    int row0 = tokb + q0 + w * 16 + (l >> 2);
    int row1 = row0 + 8;
    #pragma unroll
    for (int dt = 0; dt < 8; dt++) {
        int col = hoff + dt * 8 + (l & 3) * 2;
        float v0 = oacc[dt][0] * inv0, v1 = oacc[dt][1] * inv0;
        float v2 = oacc[dt][2] * inv1, v3 = oacc[dt][3] * inv1;
        uint32_t h0 = pack_h2(v0, v1);
        uint32_t h1 = pack_h2(v2, v3);
        *(uint32_t*)(oh + (size_t)row0 * Cc + col) = h0;
        *(uint32_t*)(oh + (size_t)row1 * Cc + col) = h1;
        *(uint32_t*)(ol + (size_t)row0 * Cc + col) =
            pack_h2(h_lo_res(v0, h0), h_hi_res(v1, h0));
        *(uint32_t*)(ol + (size_t)row1 * Cc + col) =
            pack_h2(h_lo_res(v2, h1), h_hi_res(v3, h1));
    }
}

// ---------------- host driver -----------------------------------------------
extern "C" void kernel_launch(void* const* d_in, const int* in_sizes, int n_in,
                              void* d_out, int out_size)
{
    const float* x   = (const float*)d_in[0];
    const float* Wq  = (const float*)d_in[1];
    const float* bq  = (const float*)d_in[2];
    const float* Wk  = (const float*)d_in[3];
    const float* bk  = (const float*)d_in[4];
    const float* Wv  = (const float*)d_in[5];
    const float* bv  = (const float*)d_in[6];
    const float* Wo  = (const float*)d_in[7];
    const float* bo  = (const float*)d_in[8];
    const float* Wr1 = (const float*)d_in[9];
    const float* br1 = (const float*)d_in[10];
    const float* Wr2 = (const float*)d_in[11];
    const float* br2 = (const float*)d_in[12];
    float* out = (float*)d_out;

    float* r1;
    cudaGetSymbolAddress((void**)&r1, g_r1);

    __half *xf, *rtf, *ath, *atl, *qf, *kf, *vf;
    __half *wq, *wk, *wv, *wo, *wr1;
    cudaGetSymbolAddress((void**)&xf,  g_xf);
    cudaGetSymbolAddress((void**)&rtf, g_rtf);
    cudaGetSymbolAddress((void**)&ath, g_ath); cudaGetSymbolAddress((void**)&atl, g_atl);
    cudaGetSymbolAddress((void**)&qf,  g_qf);
    cudaGetSymbolAddress((void**)&kf,  g_kf);  cudaGetSymbolAddress((void**)&vf,  g_vf);
    cudaGetSymbolAddress((void**)&wq,  g_wq);  cudaGetSymbolAddress((void**)&wk,  g_wk);
    cudaGetSymbolAddress((void**)&wv,  g_wv);  cudaGetSymbolAddress((void**)&wo,  g_wo);
    cudaGetSymbolAddress((void**)&wr1, g_wr1);

    cudaFuncSetAttribute((gemm_mma<0,2>), cudaFuncAttributeMaxDynamicSharedMemorySize, G_SMEM_BYTES);
    cudaFuncSetAttribute((gemm_mma<1,1>), cudaFuncAttributeMaxDynamicSharedMemorySize, G_SMEM_BYTES);
    cudaFuncSetAttribute((gemm_mma<3,1>), cudaFuncAttributeMaxDynamicSharedMemorySize, G_SMEM_BYTES);
    cudaFuncSetAttribute(flash_mma, cudaFuncAttributeMaxDynamicSharedMemorySize, F_SMEM_BYTES);

    dim3 gemm_grid(Cc / 128, Mm / 128);   // (8, 32)
    int act4 = (Mm * Cc) / 4;
    int w4   = (Cc * Cc) / 4;

    // #1: weight conversions (fp16 single)
    CvtW5 bat;
    bat.src[0] = Wr1; bat.dst[0] = wr1;
    bat.src[1] = Wq;  bat.dst[1] = wq;
    bat.src[2] = Wk;  bat.dst[2] = wk;
    bat.src[3] = Wv;  bat.dst[3] = wv;
    bat.src[4] = Wo;  bat.dst[4] = wo;
    cvt_w_kernel<<<dim3(w4 / 256, 5), 256>>>(bat, w4);

    // #2: x -> fp16 single
    cvt16_kernel<<<act4 / 256, 256>>>(x, xf, act4);

    // #3: mean partials
    mean_part_kernel<<<dim3(Cc / 256, 64, Bb), 256>>>(x);

    // #4 (profiled slot): r1 = tanh(x @ Wr1^T + br1), 1-term
    gemm_mma<1,1><<<gemm_grid, 256, G_SMEM_BYTES>>>(xf, nullptr, wr1, br1, r1,
                                                    nullptr, 1.0f);

    // #5: Q (pre-scaled, fp16 single out), 1-term
    gemm_mma<3,1><<<gemm_grid, 256, G_SMEM_BYTES>>>(xf, nullptr, wq, bq, nullptr,
                                                    qf, ATT_SCALE);

    // #6: mean reduce
    mean_reduce_kernel<<<(Bb * Cc) / 256, 256>>>();

    // #7: routing -> routed fp16 single
    routing_kernel<<<Mm, 128>>>(r1, Wr2, br2, x, rtf);

    // #8, #9: K, V (fp16 single out), 1-term
    gemm_mma<3,1><<<gemm_grid, 256, G_SMEM_BYTES>>>(rtf, nullptr, wk, bk, nullptr,
                                                    kf, 1.0f);
    gemm_mma<3,1><<<gemm_grid, 256, G_SMEM_BYTES>>>(rtf, nullptr, wv, bv, nullptr,
                                                    vf, 1.0f);

    // #10: flash attention (1-term S) -> att hi/lo
    flash_mma<<<dim3(Tt / 64, Hh, Bb), 128, F_SMEM_BYTES>>>(
        qf, kf, vf, ath, atl);

    // #11: output projection (fp32 out), 2-term (accuracy reserve)
    gemm_mma<0,2><<<gemm_grid, 256, G_SMEM_BYTES>>>(ath, atl, wo, bo, out,
                                                    nullptr, 1.0f);
}

// round 14
// speedup vs baseline: 1.4117x; 1.0646x over previous
#include <cuda_runtime.h>
#include <cuda_bf16.h>
#include <cuda_fp16.h>
#include <math.h>
#include <stdint.h>

// Problem constants
#define Bb 2
#define Tt 2048
#define Cc 1024
#define Hh 16
#define Dd 64
#define Mm (Bb*Tt)           // 4096 tokens
#define ATT_SCALE 0.125f     // D^-0.5

// ---------------- scratch (device globals; no allocations allowed) ----------
__device__ float g_r1[Mm*Cc];
__device__ float g_part[64*Bb*Cc];
__device__ float g_mean[Bb*Cc];

// fp16 buffers (all single precision term)
__device__ __half g_xf[Mm*Cc];
__device__ __half g_rtf[Mm*Cc];
__device__ __half g_atf[Mm*Cc];
__device__ __half g_qf[Mm*Cc];
__device__ __half g_kf[Mm*Cc],  g_vf[Mm*Cc];
__device__ __half g_wq[Cc*Cc], g_wk[Cc*Cc], g_wv[Cc*Cc];
__device__ __half g_wo[Cc*Cc], g_wr1[Cc*Cc];

// ================= PTX helpers (sm_100 baseline ISA only) ====================
__device__ __forceinline__ uint32_t smem_u32(const void* p) {
    uint32_t a;
    asm("{ .reg .u64 t; cvta.to.shared.u64 t, %1; cvt.u32.u64 %0, t; }"
        : "=r"(a) : "l"(p));
    return a;
}
__device__ __forceinline__ void cpasync16(uint32_t dst, const void* src) {
    asm volatile("cp.async.cg.shared.global [%0], [%1], 16;" :: "r"(dst), "l"(src));
}
__device__ __forceinline__ void ldsm4(uint32_t& r0, uint32_t& r1, uint32_t& r2,
                                      uint32_t& r3, uint32_t addr) {
    asm volatile("ldmatrix.sync.aligned.m8n8.x4.shared.b16 {%0,%1,%2,%3}, [%4];"
        : "=r"(r0), "=r"(r1), "=r"(r2), "=r"(r3) : "r"(addr));
}
__device__ __forceinline__ void ldsm4t(uint32_t& r0, uint32_t& r1, uint32_t& r2,
                                       uint32_t& r3, uint32_t addr) {
    asm volatile("ldmatrix.sync.aligned.m8n8.x4.trans.shared.b16 {%0,%1,%2,%3}, [%4];"
        : "=r"(r0), "=r"(r1), "=r"(r2), "=r"(r3) : "r"(addr));
}
__device__ __forceinline__ void mma16816h(float* d, const uint32_t* a, const uint32_t* b) {
    asm volatile(
        "mma.sync.aligned.m16n8k16.row.col.f32.f16.f16.f32 "
        "{%0,%1,%2,%3}, {%4,%5,%6,%7}, {%8,%9}, {%0,%1,%2,%3};"
        : "+f"(d[0]), "+f"(d[1]), "+f"(d[2]), "+f"(d[3])
        : "r"(a[0]), "r"(a[1]), "r"(a[2]), "r"(a[3]), "r"(b[0]), "r"(b[1]));
}
__device__ __forceinline__ uint32_t pack_h2(float a, float b) {
    __half2 h = __floats2half2_rn(a, b);
    return *(uint32_t*)&h;
}

// ---------------- mean pool (deterministic two-stage) -----------------------
__global__ __launch_bounds__(256) void mean_part_kernel(const float* __restrict__ x) {
    int c  = blockIdx.x * 256 + threadIdx.x;
    int b  = blockIdx.z;
    int t0 = blockIdx.y * (Tt / 64);
    float s = 0.f;
    #pragma unroll 8
    for (int tt = 0; tt < Tt / 64; tt++)
        s += x[((size_t)b * Tt + t0 + tt) * Cc + c];
    g_part[((size_t)blockIdx.y * Bb + b) * Cc + c] = s;
}

__global__ __launch_bounds__(256) void mean_reduce_kernel() {
    int idx = blockIdx.x * 256 + threadIdx.x;
    if (idx < Bb * Cc) {
        float s = 0.f;
        #pragma unroll
        for (int u = 0; u < 64; u++) s += g_part[(size_t)u * Bb * Cc + idx];
        g_mean[idx] = s * (1.0f / (float)Tt);
    }
}

// ---------------- conversions ------------------------------------------------
__global__ __launch_bounds__(256) void cvt16_kernel(
    const float* __restrict__ x, __half* __restrict__ o, int n4)
{
    int i = blockIdx.x * 256 + threadIdx.x;
    if (i >= n4) return;
    float4 v = ((const float4*)x)[i];
    uint2 p;
    p.x = pack_h2(v.x, v.y);
    p.y = pack_h2(v.z, v.w);
    ((uint2*)o)[i] = p;
}

struct CvtW5 {
    const float* src[5];
    __half* dst[5];
};
__global__ __launch_bounds__(256) void cvt_w_kernel(CvtW5 b, int n4) {
    int t = blockIdx.y;
    int i = blockIdx.x * 256 + threadIdx.x;
    if (i >= n4) return;
    float4 v = ((const float4*)b.src[t])[i];
    uint2 o;
    o.x = pack_h2(v.x, v.y);
    o.y = pack_h2(v.z, v.w);
    ((uint2*)b.dst[t])[i] = o;
}

// ================= HMMA GEMM (fp16 single-term, 3-stage pipeline) ============
// Y[M,N] = A[M,K] @ W[N,K]^T + bias.
// CTA 128x128, BK=64, stage {A, W} (36,864 B), 3 stages, 2 CTAs/SM.
// MODE 0: fp32 out; MODE 1: tanh fp32 out; MODE 3: fp16 out (x scale)
#define G_NCH 16
#define G_LD 72
#define G_TILE (128 * G_LD * 2)             // 18432 bytes per tensor tile
#define G_STAGE_BYTES (2 * G_TILE)          // 36864
#define G_SMEM_BYTES (3 * G_STAGE_BYTES)    // 110592

template<int MODE>
__global__ __launch_bounds__(256, 2) void gemm_mma(
    const __half* __restrict__ A, const __half* __restrict__ W,
    const float* __restrict__ bias, float* __restrict__ out,
    __half* __restrict__ outh, float scale)
{
    extern __shared__ __align__(16) uint8_t gsm[];
    uint32_t base = smem_u32(gsm);

    int tid = threadIdx.x;
    int wid = tid >> 5;
    int l   = tid & 31;
    int wm  = wid >> 1;
    int wn  = wid & 1;
    int m0  = blockIdx.y * 128;
    int n0  = blockIdx.x * 128;

    int lrow = tid >> 3;        // 0..31
    int lc16 = tid & 7;

    int arow = wm * 32 + (l & 15);
    int akc  = (l >> 4) * 8;
    int brow_in = (l & 7) + ((l >> 4) & 1) * 8;
    int bkc  = ((l >> 3) & 1) * 8;

    float acc[2][8][4];
    #pragma unroll
    for (int i = 0; i < 2; i++)
        #pragma unroll
        for (int j = 0; j < 8; j++)
            #pragma unroll
            for (int u = 0; u < 4; u++) acc[i][j][u] = 0.f;

    auto load_tile = [&](int c, int s) {
        int k0 = c * 64;
        uint32_t sb = base + s * G_STAGE_BYTES;
        #pragma unroll
        for (int it = 0; it < 4; it++) {
            int row = lrow + it * 32;
            uint32_t off = (row * G_LD + lc16 * 8) * 2;
            cpasync16(sb + off, A + (size_t)(m0 + row) * Cc + k0 + lc16 * 8);
            cpasync16(sb + G_TILE + off, W + (size_t)(n0 + row) * Cc + k0 + lc16 * 8);
        }
    };

    load_tile(0, 0);
    asm volatile("cp.async.commit_group;");
    load_tile(1, 1);
    asm volatile("cp.async.commit_group;");

    for (int c = 0; c < G_NCH; c++) {
        if (c < G_NCH - 1) asm volatile("cp.async.wait_group 1;");
        else               asm volatile("cp.async.wait_group 0;");
        __syncthreads();
        if (c + 2 < G_NCH) {
            load_tile(c + 2, (c + 2) % 3);
            asm volatile("cp.async.commit_group;");
        }

        uint32_t ab = base + (c % 3) * G_STAGE_BYTES;
        uint32_t wb = ab + G_TILE;
        #pragma unroll
        for (int ks = 0; ks < 4; ks++) {
            uint32_t ah[2][4];
            #pragma unroll
            for (int i = 0; i < 2; i++) {
                uint32_t ro = ((arow + i * 16) * G_LD + akc + ks * 16) * 2;
                ldsm4(ah[i][0], ah[i][1], ah[i][2], ah[i][3], ab + ro);
            }
            uint32_t wf[4][4];
            #pragma unroll
            for (int nn = 0; nn < 4; nn++)
                ldsm4(wf[nn][0], wf[nn][1], wf[nn][2], wf[nn][3],
                      wb + ((wn * 64 + nn * 16 + brow_in) * G_LD + bkc + ks * 16) * 2);
            #pragma unroll
            for (int i = 0; i < 2; i++)
                #pragma unroll
                for (int j = 0; j < 8; j++)
                    mma16816h(acc[i][j], ah[i], &wf[j >> 1][(j & 1) * 2]);
        }
    }

    // epilogue
    #pragma unroll
    for (int i = 0; i < 2; i++) {
        int row = m0 + wm * 32 + i * 16 + (l >> 2);
        #pragma unroll
        for (int j = 0; j < 8; j++) {
            int col = n0 + wn * 64 + j * 8 + (l & 3) * 2;
            float b0v = __ldg(&bias[col]);
            float b1v = __ldg(&bias[col + 1]);
            float v0 = acc[i][j][0] + b0v;
            float v1 = acc[i][j][1] + b1v;
            float v2 = acc[i][j][2] + b0v;
            float v3 = acc[i][j][3] + b1v;
            if (MODE == 1) {
                v0 = tanhf(v0); v1 = tanhf(v1);
                v2 = tanhf(v2); v3 = tanhf(v3);
            }
            if (MODE == 3) {
                v0 *= scale; v1 *= scale; v2 *= scale; v3 *= scale;
                *(uint32_t*)(outh + (size_t)row * Cc + col) = pack_h2(v0, v1);
                *(uint32_t*)(outh + (size_t)(row + 8) * Cc + col) = pack_h2(v2, v3);
            } else {
                float2 p0; p0.x = v0; p0.y = v1;
                float2 p1; p1.x = v2; p1.y = v3;
                *(float2*)(out + (size_t)row * Cc + col) = p0;
                *(float2*)(out + (size_t)(row + 8) * Cc + col) = p1;
            }
        }
    }
}

// ---------------- routing: logits -> softmax -> routed (fp16 single) --------
__global__ __launch_bounds__(128) void routing_kernel(
    const float* __restrict__ r1, const float* __restrict__ Wr2,
    const float* __restrict__ br2, const float* __restrict__ x,
    __half* __restrict__ rtf)
{
    int t = blockIdx.x;
    int b = t >> 11;
    int tid = threadIdx.x;

    const float* rrow = r1 + (size_t)t * Cc;
    float s0 = 0.f, s1 = 0.f, s2 = 0.f;
    for (int c = tid; c < Cc; c += 128) {
        float vv = rrow[c];
        s0 = fmaf(vv, Wr2[c],          s0);
        s1 = fmaf(vv, Wr2[Cc + c],     s1);
        s2 = fmaf(vv, Wr2[2 * Cc + c], s2);
    }
    #pragma unroll
    for (int o = 16; o; o >>= 1) {
        s0 += __shfl_xor_sync(0xffffffffu, s0, o);
        s1 += __shfl_xor_sync(0xffffffffu, s1, o);
        s2 += __shfl_xor_sync(0xffffffffu, s2, o);
    }
    __shared__ float red[3][4];
    __shared__ float wsh[2];
    if ((tid & 31) == 0) {
        red[0][tid >> 5] = s0; red[1][tid >> 5] = s1; red[2][tid >> 5] = s2;
    }
    __syncthreads();
    if (tid == 0) {
        float l0 = red[0][0] + red[0][1] + red[0][2] + red[0][3] + br2[0];
        float l1 = red[1][0] + red[1][1] + red[1][2] + red[1][3] + br2[1];
        float l2 = red[2][0] + red[2][1] + red[2][2] + red[2][3] + br2[2];
        float mx = fmaxf(l0, fmaxf(l1, l2));
        float e0 = expf(l0 - mx), e1 = expf(l1 - mx), e2 = expf(l2 - mx);
        float inv = 1.0f / (e0 + e1 + e2);
        wsh[0] = e0 * inv; wsh[1] = e1 * inv;
    }
    __syncthreads();
    float w0 = wsh[0], w1 = wsh[1];

    const float4* x4 = (const float4*)(x + (size_t)t * Cc);
    const float4* m4 = (const float4*)(g_mean + (size_t)b * Cc);
    uint2* ho = (uint2*)(rtf + (size_t)t * Cc);
    for (int c4 = tid; c4 < Cc / 4; c4 += 128) {
        float4 xv = x4[c4], mv = m4[c4];
        float r0 = xv.x * w0 + mv.x * w1;
        float r1v = xv.y * w0 + mv.y * w1;
        float r2 = xv.z * w0 + mv.z * w1;
        float r3 = xv.w * w0 + mv.w * w1;
        uint2 hh;
        hh.x = pack_h2(r0, r1v);
        hh.y = pack_h2(r2, r3);
        ho[c4] = hh;
    }
}

// ================= tensor-core flash attention (all fp16, 1-term) ===========
// CTA: 64 Q rows (4 warps x 16), 128 threads, KV chunks of 64, 3-stage pipe.
// 2 CTAs/SM. S = Q*K single term; PV = P x V single term. fp16 single out.
#define F_LD 72
#define FQ_HALVES (64 * F_LD)
#define FS_HALVES (64 * F_LD)
#define F_TSTAGE (2 * FS_HALVES)            // K, V
#define F_STAGE0 (FQ_HALVES)
#define F_SMEM_BYTES ((FQ_HALVES + 3 * F_TSTAGE) * 2)   // 64512

__global__ __launch_bounds__(128, 2) void flash_mma(
    const __half* __restrict__ qf,
    const __half* __restrict__ kf, const __half* __restrict__ vf,
    __half* __restrict__ oh)
{
    extern __shared__ __half fsh[];
    uint32_t fsb = smem_u32(fsh);

    int tid = threadIdx.x;
    int w   = tid >> 5;            // 0..3
    int l   = tid & 31;
    int q0  = blockIdx.x * 64;
    int h   = blockIdx.y;
    int b   = blockIdx.z;
    int tokb = b * Tt;
    int hoff = h * Dd;

    // ---- load Q, rides with chunk-0's commit group ----
    #pragma unroll
    for (int it = 0; it < 4; it++) {
        int idx = tid + it * 128;          // [0,512)
        int row = idx >> 3, c16 = idx & 7;
        uint32_t dst = fsb + (row * F_LD + c16 * 8) * 2;
        cpasync16(dst, qf + (size_t)(tokb + q0 + row) * Cc + hoff + c16 * 8);
    }
    auto load_kv = [&](int c, int s) {
        int kt0 = c * 64;
        uint32_t sb = fsb + (F_STAGE0 + s * F_TSTAGE) * 2;
        #pragma unroll
        for (int it = 0; it < 4; it++) {
            int idx = tid + it * 128;              // [0,512)
            int row = idx >> 3, c16 = idx & 7;
            uint32_t off = (row * F_LD + c16 * 8) * 2;
            cpasync16(sb + off, kf + (size_t)(tokb + kt0 + row) * Cc + hoff + c16 * 8);
            cpasync16(sb + FS_HALVES * 2 + off,
                      vf + (size_t)(tokb + kt0 + row) * Cc + hoff + c16 * 8);
        }
    };

    load_kv(0, 0);
    asm volatile("cp.async.commit_group;");
    load_kv(1, 1);
    asm volatile("cp.async.commit_group;");

    int arow = (l & 15);
    int akc  = (l >> 4) * 8;
    int brow_in = (l & 7) + ((l >> 4) & 1) * 8;
    int bkc  = ((l >> 3) & 1) * 8;
    int vrow = (l & 7) + ((l >> 3) & 1) * 8;
    int vcol = ((l >> 4) & 1) * 8;

    uint32_t qh[4][4];
    float oacc[8][4];
    #pragma unroll
    for (int j = 0; j < 8; j++)
        #pragma unroll
        for (int u = 0; u < 4; u++) oacc[j][u] = 0.f;
    float m0r = -1e30f, m1r = -1e30f, l0r = 0.f, l1r = 0.f;

    const int NCH = Tt / 64;
    for (int c = 0; c < NCH; c++) {
        if (c < NCH - 1) asm volatile("cp.async.wait_group 1;");
        else             asm volatile("cp.async.wait_group 0;");
        __syncthreads();

        if (c == 0) {
            #pragma unroll
            for (int kt = 0; kt < 4; kt++)
                ldsm4(qh[kt][0], qh[kt][1], qh[kt][2], qh[kt][3],
                      fsb + ((w * 16 + arow) * F_LD + kt * 16 + akc) * 2);
        }

        if (c + 2 < NCH) {
            load_kv(c + 2, (c + 2) % 3);
            asm volatile("cp.async.commit_group;");
        }

        uint32_t SB = F_STAGE0 + (c % 3) * F_TSTAGE;
        uint32_t KF = SB, VF = SB + FS_HALVES;

        // ---- S = Q K^T (single term) ----
        float sacc[8][4];
        #pragma unroll
        for (int j = 0; j < 8; j++)
            #pragma unroll
            for (int u = 0; u < 4; u++) sacc[j][u] = 0.f;

        #pragma unroll
        for (int ks = 0; ks < 4; ks++) {
            uint32_t kh[4][4];
            #pragma unroll
            for (int g = 0; g < 4; g++) {
                uint32_t ro = ((g * 16 + brow_in) * F_LD + bkc + ks * 16) * 2;
                ldsm4(kh[g][0], kh[g][1], kh[g][2], kh[g][3], fsb + KF * 2 + ro);
            }
            #pragma unroll
            for (int g = 0; g < 4; g++)
                #pragma unroll
                for (int sub = 0; sub < 2; sub++)
                    mma16816h(sacc[g * 2 + sub], qh[ks], &kh[g][sub * 2]);
        }

        // ---- online softmax, P packed fp16 ----
        float mx0 = -1e30f, mx1 = -1e30f;
        #pragma unroll
        for (int j = 0; j < 8; j++) {
            mx0 = fmaxf(mx0, fmaxf(sacc[j][0], sacc[j][1]));
            mx1 = fmaxf(mx1, fmaxf(sacc[j][2], sacc[j][3]));
        }
        mx0 = fmaxf(mx0, __shfl_xor_sync(0xffffffffu, mx0, 1));
        mx0 = fmaxf(mx0, __shfl_xor_sync(0xffffffffu, mx0, 2));
        mx1 = fmaxf(mx1, __shfl_xor_sync(0xffffffffu, mx1, 1));
        mx1 = fmaxf(mx1, __shfl_xor_sync(0xffffffffu, mx1, 2));
        float mn0 = fmaxf(m0r, mx0), mn1 = fmaxf(m1r, mx1);
        float cor0 = __expf(m0r - mn0), cor1 = __expf(m1r - mn1);
        m0r = mn0; m1r = mn1;

        uint32_t phf[4][4];
        float rs0 = 0.f, rs1 = 0.f;
        #pragma unroll
        for (int j = 0; j < 8; j++) {
            float e0 = __expf(sacc[j][0] - mn0);
            float e1 = __expf(sacc[j][1] - mn0);
            float e2 = __expf(sacc[j][2] - mn1);
            float e3 = __expf(sacc[j][3] - mn1);
            rs0 += e0 + e1; rs1 += e2 + e3;
            int kt = j >> 1, sl = (j & 1) * 2;
            phf[kt][sl]     = pack_h2(e0, e1);
            phf[kt][sl + 1] = pack_h2(e2, e3);
        }
        rs0 += __shfl_xor_sync(0xffffffffu, rs0, 1);
        rs0 += __shfl_xor_sync(0xffffffffu, rs0, 2);
        rs1 += __shfl_xor_sync(0xffffffffu, rs1, 1);
        rs1 += __shfl_xor_sync(0xffffffffu, rs1, 2);
        l0r = l0r * cor0 + rs0;
        l1r = l1r * cor1 + rs1;
        #pragma unroll
        for (int j = 0; j < 8; j++) {
            oacc[j][0] *= cor0; oacc[j][1] *= cor0;
            oacc[j][2] *= cor1; oacc[j][3] *= cor1;
        }

        // ---- O += P V (fp16, single term) ----
        #pragma unroll
        for (int kt = 0; kt < 4; kt++) {
            #pragma unroll
            for (int dg = 0; dg < 4; dg++) {
                uint32_t vh[4];
                uint32_t ro = ((kt * 16 + vrow) * F_LD + dg * 16 + vcol) * 2;
                ldsm4t(vh[0], vh[1], vh[2], vh[3], fsb + VF * 2 + ro);
                #pragma unroll
                for (int sub = 0; sub < 2; sub++)
                    mma16816h(oacc[dg * 2 + sub], phf[kt], &vh[sub * 2]);
            }
        }
    }

    // ---- epilogue: normalize, fp16 single, write ----
    float inv0 = 1.0f / l0r, inv1 = 1.0f / l1r;
    int row0 = tokb + q0 + w * 16 + (l >> 2);
    int row1 = row0 + 8;
    #pragma unroll
    for (int dt = 0; dt < 8; dt++) {
        int col = hoff + dt * 8 + (l & 3) * 2;
        float v0 = oacc[dt][0] * inv0, v1 = oacc[dt][1] * inv0;
        float v2 = oacc[dt][2] * inv1, v3 = oacc[dt][3] * inv1;
        *(uint32_t*)(oh + (size_t)row0 * Cc + col) = pack_h2(v0, v1);
        *(uint32_t*)(oh + (size_t)row1 * Cc + col) = pack_h2(v2, v3);
    }
}

// ---------------- host driver -----------------------------------------------
extern "C" void kernel_launch(void* const* d_in, const int* in_sizes, int n_in,
                              void* d_out, int out_size)
{
    const float* x   = (const float*)d_in[0];
    const float* Wq  = (const float*)d_in[1];
    const float* bq  = (const float*)d_in[2];
    const float* Wk  = (const float*)d_in[3];
    const float* bk  = (const float*)d_in[4];
    const float* Wv  = (const float*)d_in[5];
    const float* bv  = (const float*)d_in[6];
    const float* Wo  = (const float*)d_in[7];
    const float* bo  = (const float*)d_in[8];
    const float* Wr1 = (const float*)d_in[9];
    const float* br1 = (const float*)d_in[10];
    const float* Wr2 = (const float*)d_in[11];
    const float* br2 = (const float*)d_in[12];
    float* out = (float*)d_out;

    float* r1;
    cudaGetSymbolAddress((void**)&r1, g_r1);

    __half *xf, *rtf, *atf, *qf, *kf, *vf;
    __half *wq, *wk, *wv, *wo, *wr1;
    cudaGetSymbolAddress((void**)&xf,  g_xf);
    cudaGetSymbolAddress((void**)&rtf, g_rtf);
    cudaGetSymbolAddress((void**)&atf, g_atf);
    cudaGetSymbolAddress((void**)&qf,  g_qf);
    cudaGetSymbolAddress((void**)&kf,  g_kf);  cudaGetSymbolAddress((void**)&vf,  g_vf);
    cudaGetSymbolAddress((void**)&wq,  g_wq);  cudaGetSymbolAddress((void**)&wk,  g_wk);
    cudaGetSymbolAddress((void**)&wv,  g_wv);  cudaGetSymbolAddress((void**)&wo,  g_wo);
    cudaGetSymbolAddress((void**)&wr1, g_wr1);

    cudaFuncSetAttribute(gemm_mma<0>, cudaFuncAttributeMaxDynamicSharedMemorySize, G_SMEM_BYTES);
    cudaFuncSetAttribute(gemm_mma<1>, cudaFuncAttributeMaxDynamicSharedMemorySize, G_SMEM_BYTES);
    cudaFuncSetAttribute(gemm_mma<3>, cudaFuncAttributeMaxDynamicSharedMemorySize, G_SMEM_BYTES);
    cudaFuncSetAttribute(flash_mma, cudaFuncAttributeMaxDynamicSharedMemorySize, F_SMEM_BYTES);

    dim3 gemm_grid(Cc / 128, Mm / 128);   // (8, 32)
    int act4 = (Mm * Cc) / 4;
    int w4   = (Cc * Cc) / 4;

    // #1: weight conversions (fp16 single)
    CvtW5 bat;
    bat.src[0] = Wr1; bat.dst[0] = wr1;
    bat.src[1] = Wq;  bat.dst[1] = wq;
    bat.src[2] = Wk;  bat.dst[2] = wk;
    bat.src[3] = Wv;  bat.dst[3] = wv;
    bat.src[4] = Wo;  bat.dst[4] = wo;
    cvt_w_kernel<<<dim3(w4 / 256, 5), 256>>>(bat, w4);

    // #2: x -> fp16 single
    cvt16_kernel<<<act4 / 256, 256>>>(x, xf, act4);

    // #3: mean partials
    mean_part_kernel<<<dim3(Cc / 256, 64, Bb), 256>>>(x);

    // #4 (profiled slot): r1 = tanh(x @ Wr1^T + br1)
    gemm_mma<1><<<gemm_grid, 256, G_SMEM_BYTES>>>(xf, wr1, br1, r1,
                                                  nullptr, 1.0f);

    // #5: Q (pre-scaled, fp16 single out)
    gemm_mma<3><<<gemm_grid, 256, G_SMEM_BYTES>>>(xf, wq, bq, nullptr,
                                                  qf, ATT_SCALE);

    // #6: mean reduce
    mean_reduce_kernel<<<(Bb * Cc) / 256, 256>>>();

    // #7: routing -> routed fp16 single
    routing_kernel<<<Mm, 128>>>(r1, Wr2, br2, x, rtf);

    // #8, #9: K, V (fp16 single out)
    gemm_mma<3><<<gemm_grid, 256, G_SMEM_BYTES>>>(rtf, wk, bk, nullptr,
                                                  kf, 1.0f);
    gemm_mma<3><<<gemm_grid, 256, G_SMEM_BYTES>>>(rtf, wv, bv, nullptr,
                                                  vf, 1.0f);

    // #10: flash attention -> att fp16 single
    flash_mma<<<dim3(Tt / 64, Hh, Bb), 128, F_SMEM_BYTES>>>(
        qf, kf, vf, atf);

    // #11: output projection (fp32 out)
    gemm_mma<0><<<gemm_grid, 256, G_SMEM_BYTES>>>(atf, wo, bo, out,
                                                  nullptr, 1.0f);
}